// round 1
// baseline (speedup 1.0000x reference)
#include <cuda_runtime.h>
#include <math.h>

#define B_    64
#define S_    512
#define H_    256
#define IN_   512       // LSTM input dim (skill 256 + answer 256)
#define G4    1024      // 4*H
#define NC    1000
#define AD    80
#define MTOT  (B_*S_)   // 32768
#define RES_ELEMS (MTOT*NC)   // 32,768,000

// ---------------- scratch (device globals; no allocation allowed) ----------
__device__ float g_xproj[MTOT * G4];   // [B][S][4H]  134 MB
__device__ float g_WhhT [H_ * G4];     // [k][row]    1 MB
__device__ float g_bsum [G4];
__device__ float g_out  [MTOT * H_];   // LSTM hidden states [B][S][H]
__device__ float g_tmp80[MTOT * AD];   // tanh(out@mlpW^T + b)
__device__ float g_att  [MTOT];
__device__ float g_final[MTOT * IN_];  // [attn_cum_1 | out]

// ---------------------------------------------------------------------------
// prep: WhhT[k][row] = Whh[row][k];  bsum = bih + bhh
__global__ void prep_kernel(const float* __restrict__ Whh,
                            const float* __restrict__ bih,
                            const float* __restrict__ bhh) {
    int idx = blockIdx.x * blockDim.x + threadIdx.x;
    if (idx < H_ * G4) {
        int k = idx >> 10;          // 0..255
        int row = idx & 1023;       // 0..1023
        g_WhhT[idx] = Whh[row * H_ + k];
    }
    if (idx < G4) g_bsum[idx] = bih[idx] + bhh[idx];
}

// ---------------------------------------------------------------------------
// embed: sa_emb[b,s,:] = answer==1 ? [se|ae] : [ae|se]   (written into d_out tail)
__global__ void embed_kernel(const int* __restrict__ skill,
                             const int* __restrict__ answer,
                             const float* __restrict__ skill_emb,
                             const float* __restrict__ answer_emb,
                             float* __restrict__ sa) {
    int r = blockIdx.x;             // 0..32767  (= b*S + s)
    int t = threadIdx.x;            // 0..255
    int sk = skill[r];
    int an = answer[r];
    float se = skill_emb[sk * H_ + t];
    float ae = answer_emb[an * H_ + t];
    float* o = sa + (size_t)r * IN_;
    if (an == 1) { o[t] = se; o[H_ + t] = ae; }
    else         { o[t] = ae; o[H_ + t] = se; }
}

// ---------------------------------------------------------------------------
// Generic fp32 GEMM: C[M,N] = act( A[M,K] @ Bm[N,K]^T + bias )
// BM=BN=64, BK=16, 256 threads, 4x4 register tile. act: 0 none, 1 tanh, 2 sigmoid
__global__ void gemm_kernel(const float* __restrict__ A,
                            const float* __restrict__ Bm,
                            const float* __restrict__ bias,
                            float* __restrict__ C,
                            int M, int N, int K, int act) {
    __shared__ float As[16][64];
    __shared__ float Bs[16][64];

    int tid = threadIdx.x;
    int tx = tid & 15;              // col group
    int ty = tid >> 4;              // row group
    int rowBase = blockIdx.y * 64;
    int colBase = blockIdx.x * 64;

    int ldRow = tid >> 2;           // 0..63
    int ldCol = (tid & 3) * 4;      // 0,4,8,12

    float acc[4][4];
#pragma unroll
    for (int i = 0; i < 4; i++)
#pragma unroll
        for (int j = 0; j < 4; j++) acc[i][j] = 0.f;

    for (int k0 = 0; k0 < K; k0 += 16) {
        // load A tile (rows always valid: M multiple of 64)
        float4 av = *reinterpret_cast<const float4*>(
            A + (size_t)(rowBase + ldRow) * K + k0 + ldCol);
        As[ldCol + 0][ldRow] = av.x;
        As[ldCol + 1][ldRow] = av.y;
        As[ldCol + 2][ldRow] = av.z;
        As[ldCol + 3][ldRow] = av.w;
        // load B tile (guard N)
        int n = colBase + ldRow;
        float4 bv = make_float4(0.f, 0.f, 0.f, 0.f);
        if (n < N)
            bv = *reinterpret_cast<const float4*>(Bm + (size_t)n * K + k0 + ldCol);
        Bs[ldCol + 0][ldRow] = bv.x;
        Bs[ldCol + 1][ldRow] = bv.y;
        Bs[ldCol + 2][ldRow] = bv.z;
        Bs[ldCol + 3][ldRow] = bv.w;
        __syncthreads();

#pragma unroll
        for (int kk = 0; kk < 16; kk++) {
            float4 a4 = *reinterpret_cast<const float4*>(&As[kk][ty * 4]);
            float4 b4 = *reinterpret_cast<const float4*>(&Bs[kk][tx * 4]);
            float a[4] = {a4.x, a4.y, a4.z, a4.w};
            float b[4] = {b4.x, b4.y, b4.z, b4.w};
#pragma unroll
            for (int i = 0; i < 4; i++)
#pragma unroll
                for (int j = 0; j < 4; j++) acc[i][j] += a[i] * b[j];
        }
        __syncthreads();
    }

#pragma unroll
    for (int i = 0; i < 4; i++) {
        int row = rowBase + ty * 4 + i;
#pragma unroll
        for (int j = 0; j < 4; j++) {
            int col = colBase + tx * 4 + j;
            if (col < N) {
                float v = acc[i][j];
                if (bias) v += bias[col];
                if (act == 1) v = tanhf(v);
                else if (act == 2) v = 1.0f / (1.0f + expf(-v));
                C[(size_t)row * N + col] = v;
            }
        }
    }
}

// ---------------------------------------------------------------------------
// LSTM: one CTA per batch element. 256 threads; thread t owns hidden dim t
// (gate rows t, 256+t, 512+t, 768+t). Whh streamed (transposed) from L2.
__global__ void lstm_kernel(float* __restrict__ out) {
    int b = blockIdx.x;
    int t = threadIdx.x;
    __shared__ float h_s[2][H_];
    h_s[0][t] = 0.f;
    float c = 0.f;
    __syncthreads();

    const float* xb = g_xproj + (size_t)b * S_ * G4;
    float* ob = out + (size_t)b * S_ * H_;

    for (int s = 0; s < S_; s++) {
        const float* xr = xb + (size_t)s * G4;
        float ai = xr[t];
        float af = xr[H_ + t];
        float ag = xr[2 * H_ + t];
        float ao = xr[3 * H_ + t];
        const float* hs = h_s[s & 1];
#pragma unroll 4
        for (int k = 0; k < H_; k++) {
            float hk = hs[k];
            const float* w = g_WhhT + k * G4 + t;
            ai = fmaf(w[0],      hk, ai);
            af = fmaf(w[H_],     hk, af);
            ag = fmaf(w[2 * H_], hk, ag);
            ao = fmaf(w[3 * H_], hk, ao);
        }
        float ig = 1.0f / (1.0f + expf(-ai));
        float fg = 1.0f / (1.0f + expf(-af));
        float gg = tanhf(ag);
        float og = 1.0f / (1.0f + expf(-ao));
        c = fg * c + ig * gg;
        float h = og * tanhf(c);
        h_s[(s & 1) ^ 1][t] = h;
        ob[(size_t)s * H_ + t] = h;
        __syncthreads();
    }
}

// ---------------------------------------------------------------------------
// att[r] = dot(tmp80[r, 0:80], sim_W[0:80])   (tmp80 already tanh'd)
__global__ void attdot_kernel(const float* __restrict__ simW) {
    int warp = (blockIdx.x * blockDim.x + threadIdx.x) >> 5;
    int lane = threadIdx.x & 31;
    if (warp >= MTOT) return;
    const float* rowp = g_tmp80 + (size_t)warp * AD;
    float v = rowp[lane] * simW[lane] + rowp[lane + 32] * simW[lane + 32];
    if (lane < 16) v += rowp[lane + 64] * simW[lane + 64];
#pragma unroll
    for (int off = 16; off > 0; off >>= 1)
        v += __shfl_down_sync(0xFFFFFFFFu, v, off);
    if (lane == 0) g_att[warp] = v;
}

// ---------------------------------------------------------------------------
// prefix-softmax attention + exclusive cumsum; builds g_final = [attn_cum_1 | out]
__global__ void attnscan_kernel() {
    int b = blockIdx.x;
    int t = threadIdx.x;            // hidden dim, 0..255
    __shared__ float e_s[S_];
    __shared__ float dinv[S_];
    for (int s = t; s < S_; s += H_) e_s[s] = expf(g_att[b * S_ + s]);
    __syncthreads();
    if (t == 0) {
        float run = 0.f;
        for (int s = 0; s < S_; s++) { run += e_s[s]; dinv[s] = 1.0f / run; }
    }
    __syncthreads();

    const float* ob = g_out + (size_t)b * S_ * H_;
    float* fb = g_final + (size_t)b * S_ * IN_;
    float acc = 0.f, cum = 0.f;
    for (int s = 0; s < S_; s++) {
        float o = ob[(size_t)s * H_ + t];
        acc = fmaf(e_s[s], o, acc);
        float ao = acc * dinv[s];
        fb[(size_t)s * IN_ + t]      = cum;   // exclusive cumsum of attn_out
        fb[(size_t)s * IN_ + H_ + t] = o;
        cum += ao;
    }
}

// ---------------------------------------------------------------------------
extern "C" void kernel_launch(void* const* d_in, const int* in_sizes, int n_in,
                              void* d_out, int out_size) {
    const int*   skill      = (const int*)  d_in[0];
    const int*   answer     = (const int*)  d_in[1];
    const float* skill_emb  = (const float*)d_in[2];
    const float* answer_emb = (const float*)d_in[3];
    const float* Wih        = (const float*)d_in[4];
    const float* Whh        = (const float*)d_in[5];
    const float* bih        = (const float*)d_in[6];
    const float* bhh        = (const float*)d_in[7];
    const float* mlp_W      = (const float*)d_in[8];
    const float* mlp_b      = (const float*)d_in[9];
    const float* sim_W      = (const float*)d_in[10];
    const float* fc_W       = (const float*)d_in[11];
    const float* fc_b       = (const float*)d_in[12];

    float* res = (float*)d_out;                 // [B,S,1000]
    float* sa  = (float*)d_out + RES_ELEMS;     // [B,S,512]

    float* xproj_p; cudaGetSymbolAddress((void**)&xproj_p, g_xproj);
    float* out_p;   cudaGetSymbolAddress((void**)&out_p,   g_out);
    float* tmp80_p; cudaGetSymbolAddress((void**)&tmp80_p, g_tmp80);
    float* final_p; cudaGetSymbolAddress((void**)&final_p, g_final);
    float* bsum_p;  cudaGetSymbolAddress((void**)&bsum_p,  g_bsum);

    // 1. prep (transpose Whh, combined bias)
    prep_kernel<<<1024, 256>>>(Whh, bih, bhh);

    // 2. embeddings -> sa_emb (directly into d_out tail)
    embed_kernel<<<MTOT, 256>>>(skill, answer, skill_emb, answer_emb, sa);

    // 3. xproj = sa_emb @ Wih^T + (bih+bhh)   [32768 x 1024]
    {
        dim3 grid(G4 / 64, MTOT / 64);
        gemm_kernel<<<grid, 256>>>(sa, Wih, bsum_p, xproj_p, MTOT, G4, IN_, 0);
    }

    // 4. LSTM scan
    lstm_kernel<<<B_, H_>>>(out_p);

    // 5. tmp80 = tanh(out @ mlp_W^T + mlp_b)   [32768 x 80]
    {
        dim3 grid((AD + 63) / 64, MTOT / 64);
        gemm_kernel<<<grid, 256>>>(out_p, mlp_W, mlp_b, tmp80_p, MTOT, AD, H_, 1);
    }

    // 6. att = tmp80 @ sim_W^T
    attdot_kernel<<<(MTOT * 32 + 255) / 256, 256>>>(sim_W);

    // 7. prefix-softmax attention -> g_final = [attn_cum_1 | out]
    attnscan_kernel<<<B_, H_>>>();

    // 8. res = sigmoid(final @ fc_W^T + fc_b)   [32768 x 1000]
    {
        dim3 grid((NC + 63) / 64, MTOT / 64);
        gemm_kernel<<<grid, 256>>>(final_p, fc_W, fc_b, res, MTOT, NC, IN_, 2);
    }
}

// round 2
// speedup vs baseline: 4.3134x; 4.3134x over previous
#include <cuda_runtime.h>
#include <math.h>
#include <stdint.h>

#define B_    64
#define S_    512
#define H_    256
#define IN_   512
#define G4    1024      // 4*H
#define NC    1000
#define AD    80
#define MTOT  (B_*S_)   // 32768
#define RES_ELEMS (MTOT*NC)

// ---------------- scratch (device globals) ---------------------------------
__device__ float g_P1[1000 * G4];      // per-class xproj table (answer==1)
__device__ float g_P0[1000 * G4];      // per-class xproj table (answer==0)
__device__ float g_qb[2 * G4];         // answer-contrib + bias, per answer
__device__ float g_out  [MTOT * H_];   // LSTM hidden states
__device__ float g_tmp80[MTOT * AD];
__device__ float g_att  [MTOT];
__device__ float g_final[MTOT * IN_];  // [attn_cum_1 | out]

// ---------------- helpers ---------------------------------------------------
__device__ __forceinline__ unsigned long long fma2(unsigned long long a,
                                                   unsigned long long b,
                                                   unsigned long long c) {
    unsigned long long d;
    asm("fma.rn.f32x2 %0, %1, %2, %3;" : "=l"(d) : "l"(a), "l"(b), "l"(c));
    return d;
}
__device__ __forceinline__ float f2sum(unsigned long long v) {
    float lo, hi;
    asm("mov.b64 {%0, %1}, %2;" : "=f"(lo), "=f"(hi) : "l"(v));
    return lo + hi;
}
__device__ __forceinline__ uint32_t s2u(const void* p) {
    uint32_t a;
    asm("{ .reg .u64 t; cvta.to.shared.u64 t, %1; cvt.u32.u64 %0, t; }"
        : "=r"(a) : "l"(p));
    return a;
}
__device__ __forceinline__ void st_cluster_f32(uint32_t laddr, int crank, float v) {
    uint32_t r;
    asm volatile("mapa.shared::cluster.u32 %0, %1, %2;" : "=r"(r) : "r"(laddr), "r"(crank));
    asm volatile("st.shared::cluster.u32 [%0], %1;" :: "r"(r), "r"(__float_as_uint(v)) : "memory");
}
__device__ __forceinline__ float sigf(float x) { return 1.0f / (1.0f + expf(-x)); }

// ---------------------------------------------------------------------------
// qbias: g_qb[a][row] = bih+bhh + sum_k Wih[row][off_a + k] * answer_emb[a][k]
__global__ void qbias_kernel(const float* __restrict__ Wih,
                             const float* __restrict__ answer_emb,
                             const float* __restrict__ bih,
                             const float* __restrict__ bhh) {
    int idx = blockIdx.x * blockDim.x + threadIdx.x;
    if (idx >= 2 * G4) return;
    int a = idx >> 10;
    int row = idx & (G4 - 1);
    int off = (a == 1) ? H_ : 0;
    float s = bih[row] + bhh[row];
    const float* wr = Wih + (size_t)row * IN_ + off;
    const float* ar = answer_emb + a * H_;
#pragma unroll 4
    for (int k = 0; k < H_; k++) s += wr[k] * ar[k];
    g_qb[idx] = s;
}

// ---------------------------------------------------------------------------
// embed: sa_emb into d_out tail
__global__ void embed_kernel(const int* __restrict__ skill,
                             const int* __restrict__ answer,
                             const float* __restrict__ skill_emb,
                             const float* __restrict__ answer_emb,
                             float* __restrict__ sa) {
    int r = blockIdx.x;
    int t = threadIdx.x;
    int sk = skill[r];
    int an = answer[r];
    float se = skill_emb[sk * H_ + t];
    float ae = answer_emb[an * H_ + t];
    float* o = sa + (size_t)r * IN_;
    if (an == 1) { o[t] = se; o[H_ + t] = ae; }
    else         { o[t] = ae; o[H_ + t] = se; }
}

// ---------------------------------------------------------------------------
// fp32 GEMM with f32x2 accumulation: C[M,N] = act(A[M,K](lda) @ Bm[N,K](ldb)^T + bias)
// 64x64 tile, BK=16, 256 threads, 4x4 per thread. act: 0 none, 1 tanh, 2 sigmoid
__global__ void gemm_kernel(const float* __restrict__ A, int lda,
                            const float* __restrict__ Bm, int ldb,
                            const float* __restrict__ bias,
                            float* __restrict__ C,
                            int M, int N, int K, int act) {
    __shared__ float2 As2[8][64];
    __shared__ float2 Bs2[8][64];

    int tid = threadIdx.x;
    int tx = tid & 15;
    int ty = tid >> 4;
    int rowBase = blockIdx.y * 64;
    int colBase = blockIdx.x * 64;

    int ldRow = tid >> 2;
    int ldCol = (tid & 3) * 4;

    unsigned long long acc[4][4];
#pragma unroll
    for (int i = 0; i < 4; i++)
#pragma unroll
        for (int j = 0; j < 4; j++) acc[i][j] = 0ULL;

    for (int k0 = 0; k0 < K; k0 += 16) {
        int arow = rowBase + ldRow; if (arow > M - 1) arow = M - 1;
        float4 av = *reinterpret_cast<const float4*>(A + (size_t)arow * lda + k0 + ldCol);
        As2[ldCol / 2][ldRow]     = make_float2(av.x, av.y);
        As2[ldCol / 2 + 1][ldRow] = make_float2(av.z, av.w);
        int n = colBase + ldRow;
        float4 bv = make_float4(0.f, 0.f, 0.f, 0.f);
        if (n < N)
            bv = *reinterpret_cast<const float4*>(Bm + (size_t)n * ldb + k0 + ldCol);
        Bs2[ldCol / 2][ldRow]     = make_float2(bv.x, bv.y);
        Bs2[ldCol / 2 + 1][ldRow] = make_float2(bv.z, bv.w);
        __syncthreads();

#pragma unroll
        for (int kk2 = 0; kk2 < 8; kk2++) {
            ulonglong2 aA = *reinterpret_cast<const ulonglong2*>(&As2[kk2][ty * 4]);
            ulonglong2 aB = *reinterpret_cast<const ulonglong2*>(&As2[kk2][ty * 4 + 2]);
            unsigned long long a2[4] = {aA.x, aA.y, aB.x, aB.y};
            unsigned long long b2[4];
#pragma unroll
            for (int j = 0; j < 4; j++)
                b2[j] = *reinterpret_cast<const unsigned long long*>(&Bs2[kk2][tx + 16 * j]);
#pragma unroll
            for (int i = 0; i < 4; i++)
#pragma unroll
                for (int j = 0; j < 4; j++)
                    acc[i][j] = fma2(a2[i], b2[j], acc[i][j]);
        }
        __syncthreads();
    }

#pragma unroll
    for (int i = 0; i < 4; i++) {
        int row = rowBase + ty * 4 + i;
        if (row >= M) continue;
#pragma unroll
        for (int j = 0; j < 4; j++) {
            int col = colBase + tx + 16 * j;
            if (col < N) {
                float v = f2sum(acc[i][j]);
                if (bias) v += bias[col];
                if (act == 1) v = tanhf(v);
                else if (act == 2) v = 1.0f / (1.0f + expf(-v));
                C[(size_t)row * N + col] = v;
            }
        }
    }
}

// ---------------------------------------------------------------------------
// LSTM: 16 clusters x 8 CTAs. Cluster c handles batches [4c,4c+4).
// CTA rank j owns hidden units [32j,32j+32) (gate rows g*256+32j+u, g=0..3).
// Weights (128 rows x 256) live in SMEM, pitch 260 floats (conflict-free).
// Compute threads: t<256: r=t&127 (local row), kh=t>>7 (k half). 4 batches each.
// x comes from P tables (L2-resident): xproj never materialized.
#define WPITCH 260
#define LSTM_SMEM ((128*WPITCH + 2*4*H_ + 4*2*128 + 4*32) * 4)

__global__ void __cluster_dims__(8, 1, 1) __launch_bounds__(256, 1)
lstm_kernel(const int* __restrict__ skill, const int* __restrict__ answer,
            const float* __restrict__ Whh, float* __restrict__ out) {
    extern __shared__ float smem[];
    float* w_s   = smem;                        // [128][260]
    float* h_s   = w_s + 128 * WPITCH;          // [2][4][256]
    float* gs    = h_s + 2 * 4 * H_;            // [4 bb][2 kh][128 r]
    float* c_s   = gs + 4 * 2 * 128;            // [4][32]

    int tid  = threadIdx.x;
    int rank = blockIdx.x & 7;
    int cid  = blockIdx.x >> 3;

    // load weight slice: local row r -> global row (r>>5)*256 + 32*rank + (r&31)
    for (int idx = tid; idx < 128 * H_; idx += 256) {
        int r = idx >> 8, k = idx & (H_ - 1);
        int grow = (r >> 5) * H_ + 32 * rank + (r & 31);
        w_s[r * WPITCH + k] = Whh[(size_t)grow * H_ + k];
    }
    for (int i = tid; i < 4 * H_; i += 256) h_s[i] = 0.f;   // buffer 0
    if (tid < 128) c_s[tid] = 0.f;
    __syncthreads();
    asm volatile("barrier.cluster.arrive.aligned;" ::: "memory");
    asm volatile("barrier.cluster.wait.aligned;" ::: "memory");

    const int r  = tid & 127;
    const int kh = tid >> 7;
    const float* wrow = w_s + r * WPITCH;

    // update-phase decode
    const int uu = tid & 31;
    const int ubb = tid >> 5;     // valid when tid<128
    uint32_t h_s_u32 = s2u(h_s);

    for (int s = 0; s < S_; s++) {
        const int p = s & 1;
        const float* hb = h_s + p * 4 * H_;

        unsigned long long acc0 = 0, acc1 = 0, acc2 = 0, acc3 = 0;
        const int kbeg = kh * 32;
#pragma unroll 8
        for (int k4 = kbeg; k4 < kbeg + 32; k4++) {
            ulonglong2 w2 = *reinterpret_cast<const ulonglong2*>(wrow + k4 * 4);
            ulonglong2 h0 = *reinterpret_cast<const ulonglong2*>(hb + 0 * H_ + k4 * 4);
            ulonglong2 h1 = *reinterpret_cast<const ulonglong2*>(hb + 1 * H_ + k4 * 4);
            ulonglong2 h2 = *reinterpret_cast<const ulonglong2*>(hb + 2 * H_ + k4 * 4);
            ulonglong2 h3 = *reinterpret_cast<const ulonglong2*>(hb + 3 * H_ + k4 * 4);
            acc0 = fma2(w2.x, h0.x, acc0); acc0 = fma2(w2.y, h0.y, acc0);
            acc1 = fma2(w2.x, h1.x, acc1); acc1 = fma2(w2.y, h1.y, acc1);
            acc2 = fma2(w2.x, h2.x, acc2); acc2 = fma2(w2.y, h2.y, acc2);
            acc3 = fma2(w2.x, h3.x, acc3); acc3 = fma2(w2.y, h3.y, acc3);
        }
        gs[0 * H_ + kh * 128 + r] = f2sum(acc0);
        gs[1 * H_ + kh * 128 + r] = f2sum(acc1);
        gs[2 * H_ + kh * 128 + r] = f2sum(acc2);
        gs[3 * H_ + kh * 128 + r] = f2sum(acc3);
        __syncthreads();

        if (tid < 128) {
            int b = cid * 4 + ubb;
            int ridx = b * S_ + s;
            int sk = skill[ridx];
            int an = answer[ridx];
            const float* P = (an == 1) ? g_P1 : g_P0;
            const float* Pb = P + (size_t)sk * G4 + 32 * rank + uu;
            const float* gb = gs + ubb * H_;
            float v0 = gb[0 * 32 + uu]       + gb[128 + 0 * 32 + uu]       + Pb[0];
            float v1 = gb[1 * 32 + uu]       + gb[128 + 1 * 32 + uu]       + Pb[H_];
            float v2 = gb[2 * 32 + uu]       + gb[128 + 2 * 32 + uu]       + Pb[2 * H_];
            float v3 = gb[3 * 32 + uu]       + gb[128 + 3 * 32 + uu]       + Pb[3 * H_];
            float ig = sigf(v0), fg = sigf(v1), gg = tanhf(v2), og = sigf(v3);
            float c = fg * c_s[tid] + ig * gg;
            c_s[tid] = c;
            float h = og * tanhf(c);
            out[(size_t)b * S_ * H_ + (size_t)s * H_ + 32 * rank + uu] = h;
            uint32_t laddr = h_s_u32 +
                (((p ^ 1) * 4 * H_) + ubb * H_ + 32 * rank + uu) * 4;
#pragma unroll
            for (int c8 = 0; c8 < 8; c8++) st_cluster_f32(laddr, c8, h);
        }
        asm volatile("barrier.cluster.arrive.aligned;" ::: "memory");
        asm volatile("barrier.cluster.wait.aligned;" ::: "memory");
    }
}

// ---------------------------------------------------------------------------
__global__ void attdot_kernel(const float* __restrict__ simW) {
    int warp = (blockIdx.x * blockDim.x + threadIdx.x) >> 5;
    int lane = threadIdx.x & 31;
    if (warp >= MTOT) return;
    const float* rowp = g_tmp80 + (size_t)warp * AD;
    float v = rowp[lane] * simW[lane] + rowp[lane + 32] * simW[lane + 32];
    if (lane < 16) v += rowp[lane + 64] * simW[lane + 64];
#pragma unroll
    for (int off = 16; off > 0; off >>= 1)
        v += __shfl_down_sync(0xFFFFFFFFu, v, off);
    if (lane == 0) g_att[warp] = v;
}

// ---------------------------------------------------------------------------
__global__ void attnscan_kernel() {
    int b = blockIdx.x;
    int t = threadIdx.x;
    __shared__ float e_s[S_];
    __shared__ float dinv[S_];
    for (int s = t; s < S_; s += H_) e_s[s] = expf(g_att[b * S_ + s]);
    __syncthreads();
    if (t == 0) {
        float run = 0.f;
        for (int s = 0; s < S_; s++) { run += e_s[s]; dinv[s] = 1.0f / run; }
    }
    __syncthreads();

    const float* ob = g_out + (size_t)b * S_ * H_;
    float* fb = g_final + (size_t)b * S_ * IN_;
    float acc = 0.f, cum = 0.f;
    for (int s = 0; s < S_; s++) {
        float o = ob[(size_t)s * H_ + t];
        acc = fmaf(e_s[s], o, acc);
        float ao = acc * dinv[s];
        fb[(size_t)s * IN_ + t]      = cum;
        fb[(size_t)s * IN_ + H_ + t] = o;
        cum += ao;
    }
}

// ---------------------------------------------------------------------------
extern "C" void kernel_launch(void* const* d_in, const int* in_sizes, int n_in,
                              void* d_out, int out_size) {
    const int*   skill      = (const int*)  d_in[0];
    const int*   answer     = (const int*)  d_in[1];
    const float* skill_emb  = (const float*)d_in[2];
    const float* answer_emb = (const float*)d_in[3];
    const float* Wih        = (const float*)d_in[4];
    const float* Whh        = (const float*)d_in[5];
    const float* bih        = (const float*)d_in[6];
    const float* bhh        = (const float*)d_in[7];
    const float* mlp_W      = (const float*)d_in[8];
    const float* mlp_b      = (const float*)d_in[9];
    const float* sim_W      = (const float*)d_in[10];
    const float* fc_W       = (const float*)d_in[11];
    const float* fc_b       = (const float*)d_in[12];

    float* res = (float*)d_out;
    float* sa  = (float*)d_out + RES_ELEMS;

    float* P1_p;  cudaGetSymbolAddress((void**)&P1_p,  g_P1);
    float* P0_p;  cudaGetSymbolAddress((void**)&P0_p,  g_P0);
    float* qb_p;  cudaGetSymbolAddress((void**)&qb_p,  g_qb);
    float* out_p; cudaGetSymbolAddress((void**)&out_p, g_out);
    float* t80_p; cudaGetSymbolAddress((void**)&t80_p, g_tmp80);
    float* fin_p; cudaGetSymbolAddress((void**)&fin_p, g_final);

    cudaFuncSetAttribute(lstm_kernel,
                         cudaFuncAttributeMaxDynamicSharedMemorySize, LSTM_SMEM);

    // 1. answer-contribution + bias vectors
    qbias_kernel<<<8, 256>>>(Wih, answer_emb, bih, bhh);

    // 2. sa_emb output
    embed_kernel<<<MTOT, 256>>>(skill, answer, skill_emb, answer_emb, sa);

    // 3. per-class xproj tables: P1 / P0  [1000 x 1024]
    {
        dim3 grid(G4 / 64, (1000 + 63) / 64);
        gemm_kernel<<<grid, 256>>>(skill_emb, H_, Wih,       IN_, qb_p + G4, P1_p,
                                   1000, G4, H_, 0);
        gemm_kernel<<<grid, 256>>>(skill_emb, H_, Wih + H_,  IN_, qb_p,      P0_p,
                                   1000, G4, H_, 0);
    }

    // 4. LSTM (cluster, SMEM-resident weights)
    lstm_kernel<<<128, 256, LSTM_SMEM>>>(skill, answer, Whh, out_p);

    // 5. tmp80 = tanh(out @ mlp_W^T + mlp_b)
    {
        dim3 grid((AD + 63) / 64, MTOT / 64);
        gemm_kernel<<<grid, 256>>>(out_p, H_, mlp_W, H_, mlp_b, t80_p,
                                   MTOT, AD, H_, 1);
    }

    // 6. att = tmp80 @ sim_W^T
    attdot_kernel<<<(MTOT * 32 + 255) / 256, 256>>>(sim_W);

    // 7. prefix-softmax attention -> g_final
    attnscan_kernel<<<B_, H_>>>();

    // 8. res = sigmoid(final @ fc_W^T + fc_b)
    {
        dim3 grid((NC + 63) / 64, MTOT / 64);
        gemm_kernel<<<grid, 256>>>(fin_p, IN_, fc_W, IN_, fc_b, res,
                                   MTOT, NC, IN_, 2);
    }
}

// round 4
// speedup vs baseline: 5.8412x; 1.3542x over previous
#include <cuda_runtime.h>
#include <cuda_bf16.h>
#include <math.h>
#include <stdint.h>

#define B_    64
#define S_    512
#define H_    256
#define IN_   512
#define G4    1024      // 4*H
#define NC    1000
#define AD    80
#define MTOT  (B_*S_)   // 32768
#define RES_ELEMS (MTOT*NC)

// ---------------- scratch (device globals) ---------------------------------
__device__ float g_P1[1000 * G4];
__device__ float g_P0[1000 * G4];
__device__ float g_qb[2 * G4];
__device__ float g_out  [MTOT * H_];
__device__ float g_tmp80[MTOT * AD];
__device__ float g_att  [MTOT];
__device__ __nv_bfloat16 g_finH[MTOT * IN_];   // bf16 hi of [attn_cum_1 | out]
__device__ __nv_bfloat16 g_finL[MTOT * IN_];   // bf16 lo residual
__device__ __nv_bfloat16 g_fwH[1024 * IN_];    // fc_W hi (padded to 1024 rows)
__device__ __nv_bfloat16 g_fwL[1024 * IN_];    // fc_W lo
__device__ float g_fcb[1024];                  // fc_b padded

// ---------------- helpers ---------------------------------------------------
__device__ __forceinline__ unsigned long long fma2(unsigned long long a,
                                                   unsigned long long b,
                                                   unsigned long long c) {
    unsigned long long d;
    asm("fma.rn.f32x2 %0, %1, %2, %3;" : "=l"(d) : "l"(a), "l"(b), "l"(c));
    return d;
}
__device__ __forceinline__ float f2sum(unsigned long long v) {
    float lo, hi;
    asm("mov.b64 {%0, %1}, %2;" : "=f"(lo), "=f"(hi) : "l"(v));
    return lo + hi;
}
__device__ __forceinline__ uint32_t s2u(const void* p) {
    uint32_t a;
    asm("{ .reg .u64 t; cvta.to.shared.u64 t, %1; cvt.u32.u64 %0, t; }"
        : "=r"(a) : "l"(p));
    return a;
}
__device__ __forceinline__ void st_cluster_f32(uint32_t laddr, int crank, float v) {
    uint32_t r;
    asm volatile("mapa.shared::cluster.u32 %0, %1, %2;" : "=r"(r) : "r"(laddr), "r"(crank));
    asm volatile("st.shared::cluster.u32 [%0], %1;" :: "r"(r), "r"(__float_as_uint(v)) : "memory");
}
__device__ __forceinline__ float sigf(float x) { return 1.0f / (1.0f + expf(-x)); }

#define SWZ(o) ((o) ^ (((o) >> 3) & 0x70))

__device__ __forceinline__ void cpa16(uint32_t dst, const void* src) {
    asm volatile("cp.async.cg.shared.global [%0], [%1], 16;" :: "r"(dst), "l"(src) : "memory");
}
#define CPA_COMMIT() asm volatile("cp.async.commit_group;" ::: "memory")
template<int N> __device__ __forceinline__ void cpa_wait() {
    asm volatile("cp.async.wait_group %0;" :: "n"(N) : "memory");
}

__device__ __forceinline__ void ldsm4(uint32_t (&r)[4], uint32_t addr) {
    asm volatile("ldmatrix.sync.aligned.m8n8.x4.shared.b16 {%0,%1,%2,%3}, [%4];"
        : "=r"(r[0]), "=r"(r[1]), "=r"(r[2]), "=r"(r[3]) : "r"(addr));
}
__device__ __forceinline__ void mma16816(float (&d)[4], const uint32_t (&a)[4],
                                         uint32_t b0, uint32_t b1) {
    asm volatile("mma.sync.aligned.m16n8k16.row.col.f32.bf16.bf16.f32 "
        "{%0,%1,%2,%3}, {%4,%5,%6,%7}, {%8,%9}, {%0,%1,%2,%3};"
        : "+f"(d[0]), "+f"(d[1]), "+f"(d[2]), "+f"(d[3])
        : "r"(a[0]), "r"(a[1]), "r"(a[2]), "r"(a[3]), "r"(b0), "r"(b1));
}

// ---------------------------------------------------------------------------
__global__ void qbias_kernel(const float* __restrict__ Wih,
                             const float* __restrict__ answer_emb,
                             const float* __restrict__ bih,
                             const float* __restrict__ bhh) {
    int idx = blockIdx.x * blockDim.x + threadIdx.x;
    if (idx >= 2 * G4) return;
    int a = idx >> 10;
    int row = idx & (G4 - 1);
    int off = (a == 1) ? H_ : 0;
    float s = bih[row] + bhh[row];
    const float* wr = Wih + (size_t)row * IN_ + off;
    const float* ar = answer_emb + a * H_;
#pragma unroll 4
    for (int k = 0; k < H_; k++) s += wr[k] * ar[k];
    g_qb[idx] = s;
}

// ---------------------------------------------------------------------------
__global__ void embed_kernel(const int* __restrict__ skill,
                             const int* __restrict__ answer,
                             const float* __restrict__ skill_emb,
                             const float* __restrict__ answer_emb,
                             float* __restrict__ sa) {
    int r = blockIdx.x;
    int t = threadIdx.x;
    int sk = skill[r];
    int an = answer[r];
    float se = skill_emb[sk * H_ + t];
    float ae = answer_emb[an * H_ + t];
    float* o = sa + (size_t)r * IN_;
    if (an == 1) { o[t] = se; o[H_ + t] = ae; }
    else         { o[t] = ae; o[H_ + t] = se; }
}

// ---------------------------------------------------------------------------
__global__ void convw_kernel(const float* __restrict__ fc_W,
                             const float* __restrict__ fc_b) {
    int idx = blockIdx.x * blockDim.x + threadIdx.x;
    if (idx >= 1024 * IN_) return;
    int row = idx >> 9;
    float x = (row < NC) ? fc_W[(size_t)row * IN_ + (idx & 511)] : 0.f;
    __nv_bfloat16 h = __float2bfloat16(x);
    g_fwH[idx] = h;
    g_fwL[idx] = __float2bfloat16(x - __bfloat162float(h));
    if (idx < 1024) g_fcb[idx] = (idx < NC) ? fc_b[idx] : 0.f;
}

// ---------------------------------------------------------------------------
// fp32 GEMM (f32x2) — P tables and mlp
__global__ void gemm_kernel(const float* __restrict__ A, int lda,
                            const float* __restrict__ Bm, int ldb,
                            const float* __restrict__ bias,
                            float* __restrict__ C,
                            int M, int N, int K, int act) {
    __shared__ float2 As2[8][64];
    __shared__ float2 Bs2[8][64];

    int tid = threadIdx.x;
    int tx = tid & 15;
    int ty = tid >> 4;
    int rowBase = blockIdx.y * 64;
    int colBase = blockIdx.x * 64;
    int ldRow = tid >> 2;
    int ldCol = (tid & 3) * 4;

    unsigned long long acc[4][4];
#pragma unroll
    for (int i = 0; i < 4; i++)
#pragma unroll
        for (int j = 0; j < 4; j++) acc[i][j] = 0ULL;

    for (int k0 = 0; k0 < K; k0 += 16) {
        int arow = rowBase + ldRow; if (arow > M - 1) arow = M - 1;
        float4 av = *reinterpret_cast<const float4*>(A + (size_t)arow * lda + k0 + ldCol);
        As2[ldCol / 2][ldRow]     = make_float2(av.x, av.y);
        As2[ldCol / 2 + 1][ldRow] = make_float2(av.z, av.w);
        int n = colBase + ldRow;
        float4 bv = make_float4(0.f, 0.f, 0.f, 0.f);
        if (n < N)
            bv = *reinterpret_cast<const float4*>(Bm + (size_t)n * ldb + k0 + ldCol);
        Bs2[ldCol / 2][ldRow]     = make_float2(bv.x, bv.y);
        Bs2[ldCol / 2 + 1][ldRow] = make_float2(bv.z, bv.w);
        __syncthreads();

#pragma unroll
        for (int kk2 = 0; kk2 < 8; kk2++) {
            ulonglong2 aA = *reinterpret_cast<const ulonglong2*>(&As2[kk2][ty * 4]);
            ulonglong2 aB = *reinterpret_cast<const ulonglong2*>(&As2[kk2][ty * 4 + 2]);
            unsigned long long a2[4] = {aA.x, aA.y, aB.x, aB.y};
            unsigned long long b2[4];
#pragma unroll
            for (int j = 0; j < 4; j++)
                b2[j] = *reinterpret_cast<const unsigned long long*>(&Bs2[kk2][tx + 16 * j]);
#pragma unroll
            for (int i = 0; i < 4; i++)
#pragma unroll
                for (int j = 0; j < 4; j++)
                    acc[i][j] = fma2(a2[i], b2[j], acc[i][j]);
        }
        __syncthreads();
    }

#pragma unroll
    for (int i = 0; i < 4; i++) {
        int row = rowBase + ty * 4 + i;
        if (row >= M) continue;
#pragma unroll
        for (int j = 0; j < 4; j++) {
            int col = colBase + tx + 16 * j;
            if (col < N) {
                float v = f2sum(acc[i][j]);
                if (bias) v += bias[col];
                if (act == 1) v = tanhf(v);
                else if (act == 2) v = 1.0f / (1.0f + expf(-v));
                C[(size_t)row * N + col] = v;
            }
        }
    }
}

// ---------------------------------------------------------------------------
// LSTM (16 clusters x 8 CTAs), SMEM weights + SMEM indices + P prefetch
#define WPITCH 260
#define LSTM_SMEM ((128*WPITCH + 2*4*H_ + 4*2*128 + 4*32 + 2*4*S_) * 4)

__global__ void __cluster_dims__(8, 1, 1) __launch_bounds__(256, 1)
lstm_kernel(const int* __restrict__ skill, const int* __restrict__ answer,
            const float* __restrict__ Whh, float* __restrict__ out) {
    extern __shared__ float smem[];
    float* w_s = smem;                       // [128][260]
    float* h_s = w_s + 128 * WPITCH;         // [2][4][256]
    float* gs  = h_s + 2 * 4 * H_;           // [4][2][128]
    float* c_s = gs + 4 * 2 * 128;           // [128]
    int* sk_s  = (int*)(c_s + 4 * 32);       // [4][512]
    int* an_s  = sk_s + 4 * S_;              // [4][512]

    int tid  = threadIdx.x;
    int rank = blockIdx.x & 7;
    int cid  = blockIdx.x >> 3;

    for (int idx = tid; idx < 128 * H_; idx += 256) {
        int r = idx >> 8, k = idx & (H_ - 1);
        int grow = (r >> 5) * H_ + 32 * rank + (r & 31);
        w_s[r * WPITCH + k] = Whh[(size_t)grow * H_ + k];
    }
    for (int i = tid; i < 4 * H_; i += 256) h_s[i] = 0.f;
    if (tid < 128) c_s[tid] = 0.f;
    for (int i = tid; i < 4 * S_; i += 256) {
        int bb = i >> 9, ss = i & (S_ - 1);
        int ridx = (cid * 4 + bb) * S_ + ss;
        sk_s[i] = skill[ridx];
        an_s[i] = answer[ridx];
    }
    __syncthreads();
    asm volatile("barrier.cluster.arrive.aligned;" ::: "memory");
    asm volatile("barrier.cluster.wait.aligned;" ::: "memory");

    const int r  = tid & 127;
    const int kh = tid >> 7;
    const float* wrow = w_s + r * WPITCH;
    const int uu  = tid & 31;
    const int ubb = tid >> 5;
    uint32_t h_s_u32 = s2u(h_s);

    for (int s = 0; s < S_; s++) {
        const int p = s & 1;
        const float* hb = h_s + p * 4 * H_;

        float pv0 = 0, pv1 = 0, pv2 = 0, pv3 = 0;
        if (tid < 128) {
            int sk = sk_s[ubb * S_ + s];
            int an = an_s[ubb * S_ + s];
            const float* P = an ? g_P1 : g_P0;
            const float* Pb = P + (size_t)sk * G4 + 32 * rank + uu;
            pv0 = __ldg(Pb);
            pv1 = __ldg(Pb + H_);
            pv2 = __ldg(Pb + 2 * H_);
            pv3 = __ldg(Pb + 3 * H_);
        }

        unsigned long long acc0 = 0, acc1 = 0, acc2 = 0, acc3 = 0;
        const int kbeg = kh * 32;
#pragma unroll 8
        for (int k4 = kbeg; k4 < kbeg + 32; k4++) {
            ulonglong2 w2 = *reinterpret_cast<const ulonglong2*>(wrow + k4 * 4);
            ulonglong2 h0 = *reinterpret_cast<const ulonglong2*>(hb + 0 * H_ + k4 * 4);
            ulonglong2 h1 = *reinterpret_cast<const ulonglong2*>(hb + 1 * H_ + k4 * 4);
            ulonglong2 h2 = *reinterpret_cast<const ulonglong2*>(hb + 2 * H_ + k4 * 4);
            ulonglong2 h3 = *reinterpret_cast<const ulonglong2*>(hb + 3 * H_ + k4 * 4);
            acc0 = fma2(w2.x, h0.x, acc0); acc0 = fma2(w2.y, h0.y, acc0);
            acc1 = fma2(w2.x, h1.x, acc1); acc1 = fma2(w2.y, h1.y, acc1);
            acc2 = fma2(w2.x, h2.x, acc2); acc2 = fma2(w2.y, h2.y, acc2);
            acc3 = fma2(w2.x, h3.x, acc3); acc3 = fma2(w2.y, h3.y, acc3);
        }
        gs[0 * H_ + kh * 128 + r] = f2sum(acc0);
        gs[1 * H_ + kh * 128 + r] = f2sum(acc1);
        gs[2 * H_ + kh * 128 + r] = f2sum(acc2);
        gs[3 * H_ + kh * 128 + r] = f2sum(acc3);
        __syncthreads();

        if (tid < 128) {
            int b = cid * 4 + ubb;
            const float* gb = gs + ubb * H_;
            float v0 = gb[0 * 32 + uu] + gb[128 + 0 * 32 + uu] + pv0;
            float v1 = gb[1 * 32 + uu] + gb[128 + 1 * 32 + uu] + pv1;
            float v2 = gb[2 * 32 + uu] + gb[128 + 2 * 32 + uu] + pv2;
            float v3 = gb[3 * 32 + uu] + gb[128 + 3 * 32 + uu] + pv3;
            float ig = sigf(v0), fg = sigf(v1), gg = tanhf(v2), og = sigf(v3);
            float c = fg * c_s[tid] + ig * gg;
            c_s[tid] = c;
            float h = og * tanhf(c);
            out[(size_t)b * S_ * H_ + (size_t)s * H_ + 32 * rank + uu] = h;
            uint32_t laddr = h_s_u32 +
                (((p ^ 1) * 4 * H_) + ubb * H_ + 32 * rank + uu) * 4;
#pragma unroll
            for (int c8 = 0; c8 < 8; c8++) st_cluster_f32(laddr, c8, h);
        }
        asm volatile("barrier.cluster.arrive.aligned;" ::: "memory");
        asm volatile("barrier.cluster.wait.aligned;" ::: "memory");
    }
}

// ---------------------------------------------------------------------------
__global__ void attdot_kernel(const float* __restrict__ simW) {
    int warp = (blockIdx.x * blockDim.x + threadIdx.x) >> 5;
    int lane = threadIdx.x & 31;
    if (warp >= MTOT) return;
    const float* rowp = g_tmp80 + (size_t)warp * AD;
    float v = rowp[lane] * simW[lane] + rowp[lane + 32] * simW[lane + 32];
    if (lane < 16) v += rowp[lane + 64] * simW[lane + 64];
#pragma unroll
    for (int off = 16; off > 0; off >>= 1)
        v += __shfl_down_sync(0xFFFFFFFFu, v, off);
    if (lane == 0) g_att[warp] = v;
}

// ---------------------------------------------------------------------------
// prefix-softmax attention; emits final = [attn_cum_1 | out] as bf16 hi/lo
__global__ void attnscan_kernel() {
    int b = blockIdx.x;
    int t = threadIdx.x;
    __shared__ float e_s[S_];
    __shared__ float dinv[S_];
    for (int s = t; s < S_; s += H_) e_s[s] = expf(g_att[b * S_ + s]);
    __syncthreads();
    if (t == 0) {
        float run = 0.f;
        for (int s = 0; s < S_; s++) { run += e_s[s]; dinv[s] = 1.0f / run; }
    }
    __syncthreads();

    const float* ob = g_out + (size_t)b * S_ * H_;
    float acc = 0.f, cum = 0.f;
    for (int s = 0; s < S_; s++) {
        float o = __ldg(ob + (size_t)s * H_ + t);
        acc = fmaf(e_s[s], o, acc);
        float ao = acc * dinv[s];
        size_t base = ((size_t)b * S_ + s) * IN_;
        __nv_bfloat16 ch = __float2bfloat16(cum);
        g_finH[base + t] = ch;
        g_finL[base + t] = __float2bfloat16(cum - __bfloat162float(ch));
        __nv_bfloat16 oh = __float2bfloat16(o);
        g_finH[base + H_ + t] = oh;
        g_finL[base + H_ + t] = __float2bfloat16(o - __bfloat162float(oh));
        cum += ao;
    }
}

// ---------------------------------------------------------------------------
// fc GEMM on HMMA (mma.sync bf16, hi/lo split, 3 terms):
// res = sigmoid([finH+finL] @ [fwH+fwL]^T + fcb)
// CTA tile 128x128, K chunks of 64 (A_hi,A_lo,B_hi,B_lo 16KB each), 2 stages.
#define FC_STAGE 65536
#define FC_SMEM (2 * FC_STAGE + 1024)

__global__ void __launch_bounds__(256, 1)
fcgemm_kernel(float* __restrict__ res) {
    extern __shared__ char dsm[];
    __shared__ float fcb_s[128];
    uint32_t sb = (s2u(dsm) + 1023u) & ~1023u;

    int tid = threadIdx.x;
    int wid = tid >> 5, lane = tid & 31;
    int ntile = blockIdx.x, mtile = blockIdx.y;
    size_t mBase = (size_t)mtile * 128;
    int nBase = ntile * 128;

    if (tid < 128) fcb_s[tid] = g_fcb[nBase + tid];

    const __nv_bfloat16* srcs[4] = {
        g_finH + mBase * IN_, g_finL + mBase * IN_,
        g_fwH + (size_t)nBase * IN_, g_fwL + (size_t)nBase * IN_ };

    auto stage = [&](int c) {
        uint32_t base = sb + (uint32_t)(c & 1) * FC_STAGE;
        int k0 = c * 64;
#pragma unroll
        for (int i = 0; i < 16; i++) {
            int idx = tid + 256 * i;
            int tile = idx >> 10;
            int w = idx & 1023;          // 16B granule: row = w>>3, 8-bf16 group = w&7
            int rr = w >> 3, gg = w & 7;
            uint32_t dst = base + tile * 16384 + SWZ(w * 16);
            const __nv_bfloat16* src = srcs[tile] + (size_t)rr * IN_ + k0 + gg * 8;
            cpa16(dst, src);
        }
        CPA_COMMIT();
    };

    const int mrow0 = (wid & 1) * 64;
    const int ncol0 = (wid >> 1) * 32;

    float acc[4][4][4];
#pragma unroll
    for (int mi = 0; mi < 4; mi++)
#pragma unroll
        for (int nj = 0; nj < 4; nj++)
#pragma unroll
            for (int q = 0; q < 4; q++) acc[mi][nj][q] = 0.f;

    stage(0);
    stage(1);

    for (int c = 0; c < 8; c++) {
        if (c < 7) cpa_wait<1>(); else cpa_wait<0>();
        __syncthreads();
        uint32_t base = sb + (uint32_t)(c & 1) * FC_STAGE;

#pragma unroll
        for (int ks = 0; ks < 4; ks++) {
            int kw = ks * 16 + ((lane >> 4) << 3);   // bf16 col for this lane
            uint32_t a_h[4][4], a_l[4][4];
#pragma unroll
            for (int mi = 0; mi < 4; mi++) {
                int row = mrow0 + mi * 16 + (lane & 15);
                uint32_t off = SWZ((uint32_t)(row * 128 + kw * 2));
                ldsm4(a_h[mi], base + off);
                ldsm4(a_l[mi], base + 16384 + off);
            }
            uint32_t b_h[2][4], b_l[2][4];
#pragma unroll
            for (int bj = 0; bj < 2; bj++) {
                int nrow = ncol0 + bj * 16 + (lane & 15);
                uint32_t off = SWZ((uint32_t)(nrow * 128 + kw * 2));
                ldsm4(b_h[bj], base + 32768 + off);
                ldsm4(b_l[bj], base + 49152 + off);
            }
#pragma unroll
            for (int mi = 0; mi < 4; mi++)
#pragma unroll
                for (int nj = 0; nj < 4; nj++) {
                    int bj = nj >> 1, sel = nj & 1;
                    mma16816(acc[mi][nj], a_h[mi], b_h[bj][sel], b_h[bj][sel + 2]);
                    mma16816(acc[mi][nj], a_l[mi], b_h[bj][sel], b_h[bj][sel + 2]);
                    mma16816(acc[mi][nj], a_h[mi], b_l[bj][sel], b_l[bj][sel + 2]);
                }
        }
        __syncthreads();
        if (c + 2 < 8) stage(c + 2);
    }

    // epilogue: bias + sigmoid, float2 stores
#pragma unroll
    for (int mi = 0; mi < 4; mi++) {
        int r0 = (int)mBase + mrow0 + mi * 16 + (lane >> 2);
#pragma unroll
        for (int nj = 0; nj < 4; nj++) {
            int lc = ncol0 + nj * 8 + (lane & 3) * 2;
            int col = nBase + lc;
            if (col < NC) {
                float b0 = fcb_s[lc], b1 = fcb_s[lc + 1];
                float2 v0 = make_float2(sigf(acc[mi][nj][0] + b0),
                                        sigf(acc[mi][nj][1] + b1));
                float2 v1 = make_float2(sigf(acc[mi][nj][2] + b0),
                                        sigf(acc[mi][nj][3] + b1));
                *reinterpret_cast<float2*>(res + (size_t)r0 * NC + col) = v0;
                *reinterpret_cast<float2*>(res + (size_t)(r0 + 8) * NC + col) = v1;
            }
        }
    }
}

// ---------------------------------------------------------------------------
extern "C" void kernel_launch(void* const* d_in, const int* in_sizes, int n_in,
                              void* d_out, int out_size) {
    const int*   skill      = (const int*)  d_in[0];
    const int*   answer     = (const int*)  d_in[1];
    const float* skill_emb  = (const float*)d_in[2];
    const float* answer_emb = (const float*)d_in[3];
    const float* Wih        = (const float*)d_in[4];
    const float* Whh        = (const float*)d_in[5];
    const float* bih        = (const float*)d_in[6];
    const float* bhh        = (const float*)d_in[7];
    const float* mlp_W      = (const float*)d_in[8];
    const float* mlp_b      = (const float*)d_in[9];
    const float* sim_W      = (const float*)d_in[10];
    const float* fc_W       = (const float*)d_in[11];
    const float* fc_b       = (const float*)d_in[12];

    float* res = (float*)d_out;
    float* sa  = (float*)d_out + RES_ELEMS;

    float* P1_p;  cudaGetSymbolAddress((void**)&P1_p,  g_P1);
    float* P0_p;  cudaGetSymbolAddress((void**)&P0_p,  g_P0);
    float* qb_p;  cudaGetSymbolAddress((void**)&qb_p,  g_qb);
    float* out_p; cudaGetSymbolAddress((void**)&out_p, g_out);
    float* t80_p; cudaGetSymbolAddress((void**)&t80_p, g_tmp80);

    cudaFuncSetAttribute(lstm_kernel,
                         cudaFuncAttributeMaxDynamicSharedMemorySize, LSTM_SMEM);
    cudaFuncSetAttribute(fcgemm_kernel,
                         cudaFuncAttributeMaxDynamicSharedMemorySize, FC_SMEM);

    qbias_kernel<<<8, 256>>>(Wih, answer_emb, bih, bhh);
    embed_kernel<<<MTOT, 256>>>(skill, answer, skill_emb, answer_emb, sa);
    convw_kernel<<<(1024 * IN_ + 255) / 256, 256>>>(fc_W, fc_b);

    {
        dim3 grid(G4 / 64, (1000 + 63) / 64);
        gemm_kernel<<<grid, 256>>>(skill_emb, H_, Wih,      IN_, qb_p + G4, P1_p,
                                   1000, G4, H_, 0);
        gemm_kernel<<<grid, 256>>>(skill_emb, H_, Wih + H_, IN_, qb_p,      P0_p,
                                   1000, G4, H_, 0);
    }

    lstm_kernel<<<128, 256, LSTM_SMEM>>>(skill, answer, Whh, out_p);

    {
        dim3 grid((AD + 63) / 64, MTOT / 64);
        gemm_kernel<<<grid, 256>>>(out_p, H_, mlp_W, H_, mlp_b, t80_p,
                                   MTOT, AD, H_, 1);
    }

    attdot_kernel<<<(MTOT * 32 + 255) / 256, 256>>>(sim_W);
    attnscan_kernel<<<B_, H_>>>();

    {
        dim3 grid(8, 256);   // ntile, mtile
        fcgemm_kernel<<<grid, 256, FC_SMEM>>>(res);
    }
}

// round 5
// speedup vs baseline: 6.1335x; 1.0500x over previous
#include <cuda_runtime.h>
#include <cuda_bf16.h>
#include <math.h>
#include <stdint.h>

#define B_    64
#define S_    512
#define H_    256
#define IN_   512
#define G4    1024      // 4*H
#define NC    1000
#define AD    80
#define MTOT  (B_*S_)   // 32768
#define RES_ELEMS (MTOT*NC)

// ---------------- scratch (device globals) ---------------------------------
__device__ float g_P1[1000 * G4];
__device__ float g_P0[1000 * G4];
__device__ float g_qb[2 * G4];
__device__ float g_out  [MTOT * H_];
__device__ float g_tmp80[MTOT * AD];
__device__ float g_att  [MTOT];
__device__ __nv_bfloat16 g_finH[MTOT * IN_];   // bf16 hi of [attn_cum_1 | out]
__device__ __nv_bfloat16 g_finL[MTOT * IN_];   // bf16 lo residual
__device__ __nv_bfloat16 g_fwH[1024 * IN_];    // fc_W hi (padded to 1024 rows)
__device__ __nv_bfloat16 g_fwL[1024 * IN_];    // fc_W lo
__device__ float g_fcb[1024];                  // fc_b padded

// ---------------- helpers ---------------------------------------------------
__device__ __forceinline__ unsigned long long fma2(unsigned long long a,
                                                   unsigned long long b,
                                                   unsigned long long c) {
    unsigned long long d;
    asm("fma.rn.f32x2 %0, %1, %2, %3;" : "=l"(d) : "l"(a), "l"(b), "l"(c));
    return d;
}
__device__ __forceinline__ float f2sum(unsigned long long v) {
    float lo, hi;
    asm("mov.b64 {%0, %1}, %2;" : "=f"(lo), "=f"(hi) : "l"(v));
    return lo + hi;
}
__device__ __forceinline__ uint32_t s2u(const void* p) {
    uint32_t a;
    asm("{ .reg .u64 t; cvta.to.shared.u64 t, %1; cvt.u32.u64 %0, t; }"
        : "=r"(a) : "l"(p));
    return a;
}
// fast activations (MUFU-based)
__device__ __forceinline__ float fsig(float x) {
    return __fdividef(1.0f, 1.0f + __expf(-x));
}
__device__ __forceinline__ float ftanh(float x) {
    return __fdividef(2.0f, 1.0f + __expf(-2.0f * x)) - 1.0f;
}

#define SWZ(o) ((o) ^ (((o) >> 3) & 0x70))

__device__ __forceinline__ void cpa16(uint32_t dst, const void* src) {
    asm volatile("cp.async.cg.shared.global [%0], [%1], 16;" :: "r"(dst), "l"(src) : "memory");
}
#define CPA_COMMIT() asm volatile("cp.async.commit_group;" ::: "memory")
template<int N> __device__ __forceinline__ void cpa_wait() {
    asm volatile("cp.async.wait_group %0;" :: "n"(N) : "memory");
}

__device__ __forceinline__ void ldsm4(uint32_t (&r)[4], uint32_t addr) {
    asm volatile("ldmatrix.sync.aligned.m8n8.x4.shared.b16 {%0,%1,%2,%3}, [%4];"
        : "=r"(r[0]), "=r"(r[1]), "=r"(r[2]), "=r"(r[3]) : "r"(addr));
}
__device__ __forceinline__ void mma16816(float (&d)[4], const uint32_t (&a)[4],
                                         uint32_t b0, uint32_t b1) {
    asm volatile("mma.sync.aligned.m16n8k16.row.col.f32.bf16.bf16.f32 "
        "{%0,%1,%2,%3}, {%4,%5,%6,%7}, {%8,%9}, {%0,%1,%2,%3};"
        : "+f"(d[0]), "+f"(d[1]), "+f"(d[2]), "+f"(d[3])
        : "r"(a[0]), "r"(a[1]), "r"(a[2]), "r"(a[3]), "r"(b0), "r"(b1));
}

// ---------------------------------------------------------------------------
__global__ void qbias_kernel(const float* __restrict__ Wih,
                             const float* __restrict__ answer_emb,
                             const float* __restrict__ bih,
                             const float* __restrict__ bhh) {
    int idx = blockIdx.x * blockDim.x + threadIdx.x;
    if (idx >= 2 * G4) return;
    int a = idx >> 10;
    int row = idx & (G4 - 1);
    int off = (a == 1) ? H_ : 0;
    float s = bih[row] + bhh[row];
    const float* wr = Wih + (size_t)row * IN_ + off;
    const float* ar = answer_emb + a * H_;
#pragma unroll 4
    for (int k = 0; k < H_; k++) s += wr[k] * ar[k];
    g_qb[idx] = s;
}

// ---------------------------------------------------------------------------
__global__ void embed_kernel(const int* __restrict__ skill,
                             const int* __restrict__ answer,
                             const float* __restrict__ skill_emb,
                             const float* __restrict__ answer_emb,
                             float* __restrict__ sa) {
    int r = blockIdx.x;
    int t = threadIdx.x;
    int sk = skill[r];
    int an = answer[r];
    float se = skill_emb[sk * H_ + t];
    float ae = answer_emb[an * H_ + t];
    float* o = sa + (size_t)r * IN_;
    if (an == 1) { o[t] = se; o[H_ + t] = ae; }
    else         { o[t] = ae; o[H_ + t] = se; }
}

// ---------------------------------------------------------------------------
__global__ void convw_kernel(const float* __restrict__ fc_W,
                             const float* __restrict__ fc_b) {
    int idx = blockIdx.x * blockDim.x + threadIdx.x;
    if (idx >= 1024 * IN_) return;
    int row = idx >> 9;
    float x = (row < NC) ? fc_W[(size_t)row * IN_ + (idx & 511)] : 0.f;
    __nv_bfloat16 h = __float2bfloat16(x);
    g_fwH[idx] = h;
    g_fwL[idx] = __float2bfloat16(x - __bfloat162float(h));
    if (idx < 1024) g_fcb[idx] = (idx < NC) ? fc_b[idx] : 0.f;
}

// ---------------------------------------------------------------------------
// fp32 GEMM (f32x2) — P tables and mlp
__global__ void gemm_kernel(const float* __restrict__ A, int lda,
                            const float* __restrict__ Bm, int ldb,
                            const float* __restrict__ bias,
                            float* __restrict__ C,
                            int M, int N, int K, int act) {
    __shared__ float2 As2[8][64];
    __shared__ float2 Bs2[8][64];

    int tid = threadIdx.x;
    int tx = tid & 15;
    int ty = tid >> 4;
    int rowBase = blockIdx.y * 64;
    int colBase = blockIdx.x * 64;
    int ldRow = tid >> 2;
    int ldCol = (tid & 3) * 4;

    unsigned long long acc[4][4];
#pragma unroll
    for (int i = 0; i < 4; i++)
#pragma unroll
        for (int j = 0; j < 4; j++) acc[i][j] = 0ULL;

    for (int k0 = 0; k0 < K; k0 += 16) {
        int arow = rowBase + ldRow; if (arow > M - 1) arow = M - 1;
        float4 av = *reinterpret_cast<const float4*>(A + (size_t)arow * lda + k0 + ldCol);
        As2[ldCol / 2][ldRow]     = make_float2(av.x, av.y);
        As2[ldCol / 2 + 1][ldRow] = make_float2(av.z, av.w);
        int n = colBase + ldRow;
        float4 bv = make_float4(0.f, 0.f, 0.f, 0.f);
        if (n < N)
            bv = *reinterpret_cast<const float4*>(Bm + (size_t)n * ldb + k0 + ldCol);
        Bs2[ldCol / 2][ldRow]     = make_float2(bv.x, bv.y);
        Bs2[ldCol / 2 + 1][ldRow] = make_float2(bv.z, bv.w);
        __syncthreads();

#pragma unroll
        for (int kk2 = 0; kk2 < 8; kk2++) {
            ulonglong2 aA = *reinterpret_cast<const ulonglong2*>(&As2[kk2][ty * 4]);
            ulonglong2 aB = *reinterpret_cast<const ulonglong2*>(&As2[kk2][ty * 4 + 2]);
            unsigned long long a2[4] = {aA.x, aA.y, aB.x, aB.y};
            unsigned long long b2[4];
#pragma unroll
            for (int j = 0; j < 4; j++)
                b2[j] = *reinterpret_cast<const unsigned long long*>(&Bs2[kk2][tx + 16 * j]);
#pragma unroll
            for (int i = 0; i < 4; i++)
#pragma unroll
                for (int j = 0; j < 4; j++)
                    acc[i][j] = fma2(a2[i], b2[j], acc[i][j]);
        }
        __syncthreads();
    }

#pragma unroll
    for (int i = 0; i < 4; i++) {
        int row = rowBase + ty * 4 + i;
        if (row >= M) continue;
#pragma unroll
        for (int j = 0; j < 4; j++) {
            int col = colBase + tx + 16 * j;
            if (col < N) {
                float v = f2sum(acc[i][j]);
                if (bias) v += bias[col];
                if (act == 1) v = ftanh(v);
                else if (act == 2) v = fsig(v);
                C[(size_t)row * N + col] = v;
            }
        }
    }
}

// ---------------------------------------------------------------------------
// LSTM (16 clusters x 8 CTAs), SMEM weights + SMEM indices + P prefetch.
// This round: full unroll of the fma loop (load batching), fast activations,
// hoisted mapa remote addresses.
#define WPITCH 260
#define LSTM_SMEM ((128*WPITCH + 2*4*H_ + 4*2*128 + 4*32 + 2*4*S_) * 4)

__global__ void __cluster_dims__(8, 1, 1) __launch_bounds__(256, 1)
lstm_kernel(const int* __restrict__ skill, const int* __restrict__ answer,
            const float* __restrict__ Whh, float* __restrict__ out) {
    extern __shared__ float smem[];
    float* w_s = smem;                       // [128][260]
    float* h_s = w_s + 128 * WPITCH;         // [2][4][256]
    float* gs  = h_s + 2 * 4 * H_;           // [4][2][128]
    float* c_s = gs + 4 * 2 * 128;           // [128]
    int* sk_s  = (int*)(c_s + 4 * 32);       // [4][512]
    int* an_s  = sk_s + 4 * S_;              // [4][512]

    int tid  = threadIdx.x;
    int rank = blockIdx.x & 7;
    int cid  = blockIdx.x >> 3;

    for (int idx = tid; idx < 128 * H_; idx += 256) {
        int r = idx >> 8, k = idx & (H_ - 1);
        int grow = (r >> 5) * H_ + 32 * rank + (r & 31);
        w_s[r * WPITCH + k] = Whh[(size_t)grow * H_ + k];
    }
    for (int i = tid; i < 4 * H_; i += 256) h_s[i] = 0.f;
    if (tid < 128) c_s[tid] = 0.f;
    for (int i = tid; i < 4 * S_; i += 256) {
        int bb = i >> 9, ss = i & (S_ - 1);
        int ridx = (cid * 4 + bb) * S_ + ss;
        sk_s[i] = skill[ridx];
        an_s[i] = answer[ridx];
    }
    __syncthreads();
    asm volatile("barrier.cluster.arrive.aligned;" ::: "memory");
    asm volatile("barrier.cluster.wait.aligned;" ::: "memory");

    const int r  = tid & 127;
    const int kh = tid >> 7;
    const float* wrow = w_s + r * WPITCH;
    const int uu  = tid & 31;
    const int ubb = tid >> 5;
    uint32_t h_s_u32 = s2u(h_s);

    // hoisted remote store addresses (2 buffers x 8 ranks), update threads only
    uint32_t radr[2][8];
    if (tid < 128) {
        uint32_t off0 = h_s_u32 + (ubb * H_ + 32 * rank + uu) * 4;
#pragma unroll
        for (int c8 = 0; c8 < 8; c8++) {
            asm("mapa.shared::cluster.u32 %0, %1, %2;"
                : "=r"(radr[0][c8]) : "r"(off0), "r"(c8));
            asm("mapa.shared::cluster.u32 %0, %1, %2;"
                : "=r"(radr[1][c8]) : "r"(off0 + 4 * H_ * 4), "r"(c8));
        }
    }

    for (int s = 0; s < S_; s++) {
        const int p = s & 1;
        const float* hb = h_s + p * 4 * H_;

        float pv0 = 0, pv1 = 0, pv2 = 0, pv3 = 0;
        if (tid < 128) {
            int sk = sk_s[ubb * S_ + s];
            int an = an_s[ubb * S_ + s];
            const float* P = an ? g_P1 : g_P0;
            const float* Pb = P + (size_t)sk * G4 + 32 * rank + uu;
            pv0 = __ldg(Pb);
            pv1 = __ldg(Pb + H_);
            pv2 = __ldg(Pb + 2 * H_);
            pv3 = __ldg(Pb + 3 * H_);
        }

        unsigned long long acc0 = 0, acc1 = 0, acc2 = 0, acc3 = 0;
        const int kbeg = kh * 32;
#pragma unroll
        for (int k4 = kbeg; k4 < kbeg + 32; k4++) {
            ulonglong2 w2 = *reinterpret_cast<const ulonglong2*>(wrow + k4 * 4);
            ulonglong2 h0 = *reinterpret_cast<const ulonglong2*>(hb + 0 * H_ + k4 * 4);
            ulonglong2 h1 = *reinterpret_cast<const ulonglong2*>(hb + 1 * H_ + k4 * 4);
            ulonglong2 h2 = *reinterpret_cast<const ulonglong2*>(hb + 2 * H_ + k4 * 4);
            ulonglong2 h3 = *reinterpret_cast<const ulonglong2*>(hb + 3 * H_ + k4 * 4);
            acc0 = fma2(w2.x, h0.x, acc0); acc0 = fma2(w2.y, h0.y, acc0);
            acc1 = fma2(w2.x, h1.x, acc1); acc1 = fma2(w2.y, h1.y, acc1);
            acc2 = fma2(w2.x, h2.x, acc2); acc2 = fma2(w2.y, h2.y, acc2);
            acc3 = fma2(w2.x, h3.x, acc3); acc3 = fma2(w2.y, h3.y, acc3);
        }
        gs[0 * H_ + kh * 128 + r] = f2sum(acc0);
        gs[1 * H_ + kh * 128 + r] = f2sum(acc1);
        gs[2 * H_ + kh * 128 + r] = f2sum(acc2);
        gs[3 * H_ + kh * 128 + r] = f2sum(acc3);
        __syncthreads();

        if (tid < 128) {
            int b = cid * 4 + ubb;
            const float* gb = gs + ubb * H_;
            float v0 = gb[0 * 32 + uu] + gb[128 + 0 * 32 + uu] + pv0;
            float v1 = gb[1 * 32 + uu] + gb[128 + 1 * 32 + uu] + pv1;
            float v2 = gb[2 * 32 + uu] + gb[128 + 2 * 32 + uu] + pv2;
            float v3 = gb[3 * 32 + uu] + gb[128 + 3 * 32 + uu] + pv3;
            float ig = fsig(v0), fg = fsig(v1), gg = ftanh(v2), og = fsig(v3);
            float c = fg * c_s[tid] + ig * gg;
            c_s[tid] = c;
            float h = og * ftanh(c);
            out[(size_t)b * S_ * H_ + (size_t)s * H_ + 32 * rank + uu] = h;
            uint32_t hbits = __float_as_uint(h);
            const uint32_t* ra = radr[p ^ 1];
#pragma unroll
            for (int c8 = 0; c8 < 8; c8++)
                asm volatile("st.shared::cluster.u32 [%0], %1;"
                             :: "r"(ra[c8]), "r"(hbits) : "memory");
        }
        asm volatile("barrier.cluster.arrive.aligned;" ::: "memory");
        asm volatile("barrier.cluster.wait.aligned;" ::: "memory");
    }
}

// ---------------------------------------------------------------------------
__global__ void attdot_kernel(const float* __restrict__ simW) {
    int warp = (blockIdx.x * blockDim.x + threadIdx.x) >> 5;
    int lane = threadIdx.x & 31;
    if (warp >= MTOT) return;
    const float* rowp = g_tmp80 + (size_t)warp * AD;
    float v = rowp[lane] * simW[lane] + rowp[lane + 32] * simW[lane + 32];
    if (lane < 16) v += rowp[lane + 64] * simW[lane + 64];
#pragma unroll
    for (int off = 16; off > 0; off >>= 1)
        v += __shfl_down_sync(0xFFFFFFFFu, v, off);
    if (lane == 0) g_att[warp] = v;
}

// ---------------------------------------------------------------------------
// prefix-softmax attention; emits final = [attn_cum_1 | out] as bf16 hi/lo
__global__ void attnscan_kernel() {
    int b = blockIdx.x;
    int t = threadIdx.x;
    __shared__ float e_s[S_];
    __shared__ float dinv[S_];
    for (int s = t; s < S_; s += H_) e_s[s] = __expf(g_att[b * S_ + s]);
    __syncthreads();
    if (t == 0) {
        float run = 0.f;
        for (int s = 0; s < S_; s++) { run += e_s[s]; dinv[s] = __fdividef(1.0f, run); }
    }
    __syncthreads();

    const float* ob = g_out + (size_t)b * S_ * H_;
    float acc = 0.f, cum = 0.f;
    for (int s = 0; s < S_; s++) {
        float o = __ldg(ob + (size_t)s * H_ + t);
        acc = fmaf(e_s[s], o, acc);
        float ao = acc * dinv[s];
        size_t base = ((size_t)b * S_ + s) * IN_;
        __nv_bfloat16 ch = __float2bfloat16(cum);
        g_finH[base + t] = ch;
        g_finL[base + t] = __float2bfloat16(cum - __bfloat162float(ch));
        __nv_bfloat16 oh = __float2bfloat16(o);
        g_finH[base + H_ + t] = oh;
        g_finL[base + H_ + t] = __float2bfloat16(o - __bfloat162float(oh));
        cum += ao;
    }
}

// ---------------------------------------------------------------------------
// fc GEMM on HMMA (mma.sync bf16, hi/lo split, 3 terms)
#define FC_STAGE 65536
#define FC_SMEM (2 * FC_STAGE + 1024)

__global__ void __launch_bounds__(256, 1)
fcgemm_kernel(float* __restrict__ res) {
    extern __shared__ char dsm[];
    __shared__ float fcb_s[128];
    uint32_t sb = (s2u(dsm) + 1023u) & ~1023u;

    int tid = threadIdx.x;
    int wid = tid >> 5, lane = tid & 31;
    int ntile = blockIdx.x, mtile = blockIdx.y;
    size_t mBase = (size_t)mtile * 128;
    int nBase = ntile * 128;

    if (tid < 128) fcb_s[tid] = g_fcb[nBase + tid];

    const __nv_bfloat16* srcs[4] = {
        g_finH + mBase * IN_, g_finL + mBase * IN_,
        g_fwH + (size_t)nBase * IN_, g_fwL + (size_t)nBase * IN_ };

    auto stage = [&](int c) {
        uint32_t base = sb + (uint32_t)(c & 1) * FC_STAGE;
        int k0 = c * 64;
#pragma unroll
        for (int i = 0; i < 16; i++) {
            int idx = tid + 256 * i;
            int tile = idx >> 10;
            int w = idx & 1023;
            int rr = w >> 3, gg = w & 7;
            uint32_t dst = base + tile * 16384 + SWZ(w * 16);
            const __nv_bfloat16* src = srcs[tile] + (size_t)rr * IN_ + k0 + gg * 8;
            cpa16(dst, src);
        }
        CPA_COMMIT();
    };

    const int mrow0 = (wid & 1) * 64;
    const int ncol0 = (wid >> 1) * 32;

    float acc[4][4][4];
#pragma unroll
    for (int mi = 0; mi < 4; mi++)
#pragma unroll
        for (int nj = 0; nj < 4; nj++)
#pragma unroll
            for (int q = 0; q < 4; q++) acc[mi][nj][q] = 0.f;

    stage(0);
    stage(1);

    for (int c = 0; c < 8; c++) {
        if (c < 7) cpa_wait<1>(); else cpa_wait<0>();
        __syncthreads();
        uint32_t base = sb + (uint32_t)(c & 1) * FC_STAGE;

#pragma unroll
        for (int ks = 0; ks < 4; ks++) {
            int kw = ks * 16 + ((lane >> 4) << 3);
            uint32_t a_h[4][4], a_l[4][4];
#pragma unroll
            for (int mi = 0; mi < 4; mi++) {
                int row = mrow0 + mi * 16 + (lane & 15);
                uint32_t off = SWZ((uint32_t)(row * 128 + kw * 2));
                ldsm4(a_h[mi], base + off);
                ldsm4(a_l[mi], base + 16384 + off);
            }
            uint32_t b_h[2][4], b_l[2][4];
#pragma unroll
            for (int bj = 0; bj < 2; bj++) {
                int nrow = ncol0 + bj * 16 + (lane & 15);
                uint32_t off = SWZ((uint32_t)(nrow * 128 + kw * 2));
                ldsm4(b_h[bj], base + 32768 + off);
                ldsm4(b_l[bj], base + 49152 + off);
            }
#pragma unroll
            for (int mi = 0; mi < 4; mi++)
#pragma unroll
                for (int nj = 0; nj < 4; nj++) {
                    int bj = nj >> 1, sel = nj & 1;
                    mma16816(acc[mi][nj], a_h[mi], b_h[bj][sel], b_h[bj][sel + 2]);
                    mma16816(acc[mi][nj], a_l[mi], b_h[bj][sel], b_h[bj][sel + 2]);
                    mma16816(acc[mi][nj], a_h[mi], b_l[bj][sel], b_l[bj][sel + 2]);
                }
        }
        __syncthreads();
        if (c + 2 < 8) stage(c + 2);
    }

#pragma unroll
    for (int mi = 0; mi < 4; mi++) {
        int r0 = (int)mBase + mrow0 + mi * 16 + (lane >> 2);
#pragma unroll
        for (int nj = 0; nj < 4; nj++) {
            int lc = ncol0 + nj * 8 + (lane & 3) * 2;
            int col = nBase + lc;
            if (col < NC) {
                float b0 = fcb_s[lc], b1 = fcb_s[lc + 1];
                float2 v0 = make_float2(fsig(acc[mi][nj][0] + b0),
                                        fsig(acc[mi][nj][1] + b1));
                float2 v1 = make_float2(fsig(acc[mi][nj][2] + b0),
                                        fsig(acc[mi][nj][3] + b1));
                *reinterpret_cast<float2*>(res + (size_t)r0 * NC + col) = v0;
                *reinterpret_cast<float2*>(res + (size_t)(r0 + 8) * NC + col) = v1;
            }
        }
    }
}

// ---------------------------------------------------------------------------
extern "C" void kernel_launch(void* const* d_in, const int* in_sizes, int n_in,
                              void* d_out, int out_size) {
    const int*   skill      = (const int*)  d_in[0];
    const int*   answer     = (const int*)  d_in[1];
    const float* skill_emb  = (const float*)d_in[2];
    const float* answer_emb = (const float*)d_in[3];
    const float* Wih        = (const float*)d_in[4];
    const float* Whh        = (const float*)d_in[5];
    const float* bih        = (const float*)d_in[6];
    const float* bhh        = (const float*)d_in[7];
    const float* mlp_W      = (const float*)d_in[8];
    const float* mlp_b      = (const float*)d_in[9];
    const float* sim_W      = (const float*)d_in[10];
    const float* fc_W       = (const float*)d_in[11];
    const float* fc_b       = (const float*)d_in[12];

    float* res = (float*)d_out;
    float* sa  = (float*)d_out + RES_ELEMS;

    float* P1_p;  cudaGetSymbolAddress((void**)&P1_p,  g_P1);
    float* P0_p;  cudaGetSymbolAddress((void**)&P0_p,  g_P0);
    float* qb_p;  cudaGetSymbolAddress((void**)&qb_p,  g_qb);
    float* out_p; cudaGetSymbolAddress((void**)&out_p, g_out);
    float* t80_p; cudaGetSymbolAddress((void**)&t80_p, g_tmp80);

    cudaFuncSetAttribute(lstm_kernel,
                         cudaFuncAttributeMaxDynamicSharedMemorySize, LSTM_SMEM);
    cudaFuncSetAttribute(fcgemm_kernel,
                         cudaFuncAttributeMaxDynamicSharedMemorySize, FC_SMEM);

    qbias_kernel<<<8, 256>>>(Wih, answer_emb, bih, bhh);
    embed_kernel<<<MTOT, 256>>>(skill, answer, skill_emb, answer_emb, sa);
    convw_kernel<<<(1024 * IN_ + 255) / 256, 256>>>(fc_W, fc_b);

    {
        dim3 grid(G4 / 64, (1000 + 63) / 64);
        gemm_kernel<<<grid, 256>>>(skill_emb, H_, Wih,      IN_, qb_p + G4, P1_p,
                                   1000, G4, H_, 0);
        gemm_kernel<<<grid, 256>>>(skill_emb, H_, Wih + H_, IN_, qb_p,      P0_p,
                                   1000, G4, H_, 0);
    }

    lstm_kernel<<<128, 256, LSTM_SMEM>>>(skill, answer, Whh, out_p);

    {
        dim3 grid((AD + 63) / 64, MTOT / 64);
        gemm_kernel<<<grid, 256>>>(out_p, H_, mlp_W, H_, mlp_b, t80_p,
                                   MTOT, AD, H_, 1);
    }

    attdot_kernel<<<(MTOT * 32 + 255) / 256, 256>>>(sim_W);
    attnscan_kernel<<<B_, H_>>>();

    {
        dim3 grid(8, 256);   // ntile, mtile
        fcgemm_kernel<<<grid, 256, FC_SMEM>>>(res);
    }
}

// round 6
// speedup vs baseline: 8.5346x; 1.3915x over previous
#include <cuda_runtime.h>
#include <cuda_bf16.h>
#include <math.h>
#include <stdint.h>

#define B_    64
#define S_    512
#define H_    256
#define IN_   512
#define G4    1024      // 4*H
#define NC    1000
#define AD    80
#define MTOT  (B_*S_)   // 32768
#define RES_ELEMS (MTOT*NC)

// ---------------- scratch (device globals) ---------------------------------
__device__ float g_P1[1000 * G4];
__device__ float g_P0[1000 * G4];
__device__ float g_qb[2 * G4];
__device__ float g_out  [MTOT * H_];
__device__ float g_tmp80[MTOT * AD];
__device__ float g_att  [MTOT];
__device__ __nv_bfloat16 g_finH[MTOT * IN_];   // bf16 hi of [attn_cum_1 | out]
__device__ __nv_bfloat16 g_finL[MTOT * IN_];   // bf16 lo residual
__device__ __nv_bfloat16 g_fwH[1024 * IN_];    // fc_W hi (padded to 1024 rows)
__device__ __nv_bfloat16 g_fwL[1024 * IN_];    // fc_W lo
__device__ float g_fcb[1024];                  // fc_b padded

// ---------------- helpers ---------------------------------------------------
__device__ __forceinline__ unsigned long long fma2(unsigned long long a,
                                                   unsigned long long b,
                                                   unsigned long long c) {
    unsigned long long d;
    asm("fma.rn.f32x2 %0, %1, %2, %3;" : "=l"(d) : "l"(a), "l"(b), "l"(c));
    return d;
}
__device__ __forceinline__ float f2sum(unsigned long long v) {
    float lo, hi;
    asm("mov.b64 {%0, %1}, %2;" : "=f"(lo), "=f"(hi) : "l"(v));
    return lo + hi;
}
__device__ __forceinline__ uint32_t s2u(const void* p) {
    uint32_t a;
    asm("{ .reg .u64 t; cvta.to.shared.u64 t, %1; cvt.u32.u64 %0, t; }"
        : "=r"(a) : "l"(p));
    return a;
}
// fast activations (MUFU-based)
__device__ __forceinline__ float fsig(float x) {
    return __fdividef(1.0f, 1.0f + __expf(-x));
}
__device__ __forceinline__ float ftanh(float x) {
    return __fdividef(2.0f, 1.0f + __expf(-2.0f * x)) - 1.0f;
}

#define SWZ(o) ((o) ^ (((o) >> 3) & 0x70))

__device__ __forceinline__ void cpa16(uint32_t dst, const void* src) {
    asm volatile("cp.async.cg.shared.global [%0], [%1], 16;" :: "r"(dst), "l"(src) : "memory");
}
#define CPA_COMMIT() asm volatile("cp.async.commit_group;" ::: "memory")
template<int N> __device__ __forceinline__ void cpa_wait() {
    asm volatile("cp.async.wait_group %0;" :: "n"(N) : "memory");
}

__device__ __forceinline__ void ldsm4(uint32_t (&r)[4], uint32_t addr) {
    asm volatile("ldmatrix.sync.aligned.m8n8.x4.shared.b16 {%0,%1,%2,%3}, [%4];"
        : "=r"(r[0]), "=r"(r[1]), "=r"(r[2]), "=r"(r[3]) : "r"(addr));
}
__device__ __forceinline__ void mma16816(float (&d)[4], const uint32_t (&a)[4],
                                         uint32_t b0, uint32_t b1) {
    asm volatile("mma.sync.aligned.m16n8k16.row.col.f32.bf16.bf16.f32 "
        "{%0,%1,%2,%3}, {%4,%5,%6,%7}, {%8,%9}, {%0,%1,%2,%3};"
        : "+f"(d[0]), "+f"(d[1]), "+f"(d[2]), "+f"(d[3])
        : "r"(a[0]), "r"(a[1]), "r"(a[2]), "r"(a[3]), "r"(b0), "r"(b1));
}

// ---------------------------------------------------------------------------
__global__ void qbias_kernel(const float* __restrict__ Wih,
                             const float* __restrict__ answer_emb,
                             const float* __restrict__ bih,
                             const float* __restrict__ bhh) {
    int idx = blockIdx.x * blockDim.x + threadIdx.x;
    if (idx >= 2 * G4) return;
    int a = idx >> 10;
    int row = idx & (G4 - 1);
    int off = (a == 1) ? H_ : 0;
    float s = bih[row] + bhh[row];
    const float* wr = Wih + (size_t)row * IN_ + off;
    const float* ar = answer_emb + a * H_;
#pragma unroll 4
    for (int k = 0; k < H_; k++) s += wr[k] * ar[k];
    g_qb[idx] = s;
}

// ---------------------------------------------------------------------------
__global__ void embed_kernel(const int* __restrict__ skill,
                             const int* __restrict__ answer,
                             const float* __restrict__ skill_emb,
                             const float* __restrict__ answer_emb,
                             float* __restrict__ sa) {
    int r = blockIdx.x;
    int t = threadIdx.x;
    int sk = skill[r];
    int an = answer[r];
    float se = skill_emb[sk * H_ + t];
    float ae = answer_emb[an * H_ + t];
    float* o = sa + (size_t)r * IN_;
    if (an == 1) { o[t] = se; o[H_ + t] = ae; }
    else         { o[t] = ae; o[H_ + t] = se; }
}

// ---------------------------------------------------------------------------
__global__ void convw_kernel(const float* __restrict__ fc_W,
                             const float* __restrict__ fc_b) {
    int idx = blockIdx.x * blockDim.x + threadIdx.x;
    if (idx >= 1024 * IN_) return;
    int row = idx >> 9;
    float x = (row < NC) ? fc_W[(size_t)row * IN_ + (idx & 511)] : 0.f;
    __nv_bfloat16 h = __float2bfloat16(x);
    g_fwH[idx] = h;
    g_fwL[idx] = __float2bfloat16(x - __bfloat162float(h));
    if (idx < 1024) g_fcb[idx] = (idx < NC) ? fc_b[idx] : 0.f;
}

// ---------------------------------------------------------------------------
// fp32 GEMM (f32x2) — P tables and mlp
__global__ void gemm_kernel(const float* __restrict__ A, int lda,
                            const float* __restrict__ Bm, int ldb,
                            const float* __restrict__ bias,
                            float* __restrict__ C,
                            int M, int N, int K, int act) {
    __shared__ float2 As2[8][64];
    __shared__ float2 Bs2[8][64];

    int tid = threadIdx.x;
    int tx = tid & 15;
    int ty = tid >> 4;
    int rowBase = blockIdx.y * 64;
    int colBase = blockIdx.x * 64;
    int ldRow = tid >> 2;
    int ldCol = (tid & 3) * 4;

    unsigned long long acc[4][4];
#pragma unroll
    for (int i = 0; i < 4; i++)
#pragma unroll
        for (int j = 0; j < 4; j++) acc[i][j] = 0ULL;

    for (int k0 = 0; k0 < K; k0 += 16) {
        int arow = rowBase + ldRow; if (arow > M - 1) arow = M - 1;
        float4 av = *reinterpret_cast<const float4*>(A + (size_t)arow * lda + k0 + ldCol);
        As2[ldCol / 2][ldRow]     = make_float2(av.x, av.y);
        As2[ldCol / 2 + 1][ldRow] = make_float2(av.z, av.w);
        int n = colBase + ldRow;
        float4 bv = make_float4(0.f, 0.f, 0.f, 0.f);
        if (n < N)
            bv = *reinterpret_cast<const float4*>(Bm + (size_t)n * ldb + k0 + ldCol);
        Bs2[ldCol / 2][ldRow]     = make_float2(bv.x, bv.y);
        Bs2[ldCol / 2 + 1][ldRow] = make_float2(bv.z, bv.w);
        __syncthreads();

#pragma unroll
        for (int kk2 = 0; kk2 < 8; kk2++) {
            ulonglong2 aA = *reinterpret_cast<const ulonglong2*>(&As2[kk2][ty * 4]);
            ulonglong2 aB = *reinterpret_cast<const ulonglong2*>(&As2[kk2][ty * 4 + 2]);
            unsigned long long a2[4] = {aA.x, aA.y, aB.x, aB.y};
            unsigned long long b2[4];
#pragma unroll
            for (int j = 0; j < 4; j++)
                b2[j] = *reinterpret_cast<const unsigned long long*>(&Bs2[kk2][tx + 16 * j]);
#pragma unroll
            for (int i = 0; i < 4; i++)
#pragma unroll
                for (int j = 0; j < 4; j++)
                    acc[i][j] = fma2(a2[i], b2[j], acc[i][j]);
        }
        __syncthreads();
    }

#pragma unroll
    for (int i = 0; i < 4; i++) {
        int row = rowBase + ty * 4 + i;
        if (row >= M) continue;
#pragma unroll
        for (int j = 0; j < 4; j++) {
            int col = colBase + tx + 16 * j;
            if (col < N) {
                float v = f2sum(acc[i][j]);
                if (bias) v += bias[col];
                if (act == 1) v = ftanh(v);
                else if (act == 2) v = fsig(v);
                C[(size_t)row * N + col] = v;
            }
        }
    }
}

// ---------------------------------------------------------------------------
// LSTM v3: 16 clusters x 8 CTAs x 4 batches. Whh lives in REGISTERS.
// Warp w owns k-slice [32w, 32w+32); lane l owns unit (rank*32 + l), all 4 gates
// -> 128 weight floats per thread. Per step: broadcast h from SMEM, 256 fma2,
// cross-warp reduce via 16KB gpart, update by threads 0-127, cluster h exchange.
#define LSTM_SMEM ((2*4*H_ + 8*4*4*32 + 128 + 2*4*S_) * 4)

__global__ void __cluster_dims__(8, 1, 1) __launch_bounds__(256, 1)
lstm_kernel(const int* __restrict__ skill, const int* __restrict__ answer,
            const float* __restrict__ Whh, float* __restrict__ out) {
    extern __shared__ float smem[];
    float* h_s = smem;                   // [2][4][256]
    float* gp  = h_s + 2 * 4 * H_;       // [8 w][4 g][4 b][32 l]
    float* c_s = gp + 8 * 4 * 4 * 32;    // [128]
    int* sk_s  = (int*)(c_s + 128);      // [4][512]
    int* an_s  = sk_s + 4 * S_;          // [4][512]

    int tid  = threadIdx.x;
    int w    = tid >> 5;
    int l    = tid & 31;
    int rank = blockIdx.x & 7;
    int cid  = blockIdx.x >> 3;

    // weights -> registers (one-time)
    float2 wreg[4][16];
#pragma unroll
    for (int g = 0; g < 4; g++) {
        const float* rowp = Whh + (size_t)(g * H_ + rank * 32 + l) * H_ + w * 32;
#pragma unroll
        for (int j = 0; j < 16; j++)
            wreg[g][j] = *reinterpret_cast<const float2*>(rowp + j * 2);
    }

    for (int i = tid; i < 4 * H_; i += 256) h_s[i] = 0.f;   // buffer 0
    if (tid < 128) c_s[tid] = 0.f;
    for (int i = tid; i < 4 * S_; i += 256) {
        int bb = i >> 9, ss = i & (S_ - 1);
        int ridx = (cid * 4 + bb) * S_ + ss;
        sk_s[i] = skill[ridx];
        an_s[i] = answer[ridx];
    }
    __syncthreads();
    asm volatile("barrier.cluster.arrive.aligned;" ::: "memory");
    asm volatile("barrier.cluster.wait.aligned;" ::: "memory");

    const int uu  = tid & 31;
    const int ubb = tid >> 5;            // valid for tid<128
    uint32_t h_s_u32 = s2u(h_s);

    // hoisted remote store addresses (2 buffers x 8 ranks) for update threads
    uint32_t radr[2][8];
    if (tid < 128) {
        uint32_t off0 = h_s_u32 + (ubb * H_ + 32 * rank + uu) * 4;
#pragma unroll
        for (int c8 = 0; c8 < 8; c8++) {
            asm("mapa.shared::cluster.u32 %0, %1, %2;"
                : "=r"(radr[0][c8]) : "r"(off0), "r"(c8));
            asm("mapa.shared::cluster.u32 %0, %1, %2;"
                : "=r"(radr[1][c8]) : "r"(off0 + 4 * H_ * 4), "r"(c8));
        }
    }

    for (int s = 0; s < S_; s++) {
        const int p = s & 1;
        const float* hb = h_s + p * 4 * H_ + w * 32;

        // prefetch P rows for update phase
        float pv[4] = {0.f, 0.f, 0.f, 0.f};
        if (tid < 128) {
            int sk = sk_s[ubb * S_ + s];
            int an = an_s[ubb * S_ + s];
            const float* P = an ? g_P1 : g_P0;
            const float* Pb = P + (size_t)sk * G4 + 32 * rank + uu;
            pv[0] = __ldg(Pb);
            pv[1] = __ldg(Pb + H_);
            pv[2] = __ldg(Pb + 2 * H_);
            pv[3] = __ldg(Pb + 3 * H_);
        }

        // fma over this warp's k-slice (broadcast h loads, register weights)
        unsigned long long acc[4][4];
#pragma unroll
        for (int g = 0; g < 4; g++)
#pragma unroll
            for (int b = 0; b < 4; b++) acc[g][b] = 0ULL;

#pragma unroll
        for (int k4 = 0; k4 < 8; k4++) {
            ulonglong2 hv[4];
#pragma unroll
            for (int b = 0; b < 4; b++)
                hv[b] = *reinterpret_cast<const ulonglong2*>(hb + b * H_ + k4 * 4);
#pragma unroll
            for (int g = 0; g < 4; g++) {
                unsigned long long w0 =
                    *reinterpret_cast<const unsigned long long*>(&wreg[g][k4 * 2]);
                unsigned long long w1 =
                    *reinterpret_cast<const unsigned long long*>(&wreg[g][k4 * 2 + 1]);
#pragma unroll
                for (int b = 0; b < 4; b++) {
                    acc[g][b] = fma2(w0, hv[b].x, acc[g][b]);
                    acc[g][b] = fma2(w1, hv[b].y, acc[g][b]);
                }
            }
        }
        // write partials: gp[w][g][b][l]
#pragma unroll
        for (int g = 0; g < 4; g++)
#pragma unroll
            for (int b = 0; b < 4; b++)
                gp[((w * 4 + g) * 4 + b) * 32 + l] = f2sum(acc[g][b]);
        __syncthreads();

        if (tid < 128) {
            float v[4];
#pragma unroll
            for (int g = 0; g < 4; g++) {
                float sum = pv[g];
#pragma unroll
                for (int ww = 0; ww < 8; ww++)
                    sum += gp[((ww * 4 + g) * 4 + ubb) * 32 + uu];
                v[g] = sum;
            }
            float ig = fsig(v[0]), fg = fsig(v[1]);
            float gg = ftanh(v[2]), og = fsig(v[3]);
            float c = fg * c_s[tid] + ig * gg;
            c_s[tid] = c;
            float h = og * ftanh(c);
            int b = cid * 4 + ubb;
            out[(size_t)b * S_ * H_ + (size_t)s * H_ + 32 * rank + uu] = h;
            uint32_t hbits = __float_as_uint(h);
            const uint32_t* ra = radr[p ^ 1];
#pragma unroll
            for (int c8 = 0; c8 < 8; c8++)
                asm volatile("st.shared::cluster.u32 [%0], %1;"
                             :: "r"(ra[c8]), "r"(hbits) : "memory");
        }
        asm volatile("barrier.cluster.arrive.aligned;" ::: "memory");
        asm volatile("barrier.cluster.wait.aligned;" ::: "memory");
    }
}

// ---------------------------------------------------------------------------
__global__ void attdot_kernel(const float* __restrict__ simW) {
    int warp = (blockIdx.x * blockDim.x + threadIdx.x) >> 5;
    int lane = threadIdx.x & 31;
    if (warp >= MTOT) return;
    const float* rowp = g_tmp80 + (size_t)warp * AD;
    float v = rowp[lane] * simW[lane] + rowp[lane + 32] * simW[lane + 32];
    if (lane < 16) v += rowp[lane + 64] * simW[lane + 64];
#pragma unroll
    for (int off = 16; off > 0; off >>= 1)
        v += __shfl_down_sync(0xFFFFFFFFu, v, off);
    if (lane == 0) g_att[warp] = v;
}

// ---------------------------------------------------------------------------
// prefix-softmax attention; emits final = [attn_cum_1 | out] as bf16 hi/lo
__global__ void attnscan_kernel() {
    int b = blockIdx.x;
    int t = threadIdx.x;
    __shared__ float e_s[S_];
    __shared__ float dinv[S_];
    for (int s = t; s < S_; s += H_) e_s[s] = __expf(g_att[b * S_ + s]);
    __syncthreads();
    if (t == 0) {
        float run = 0.f;
        for (int s = 0; s < S_; s++) { run += e_s[s]; dinv[s] = __fdividef(1.0f, run); }
    }
    __syncthreads();

    const float* ob = g_out + (size_t)b * S_ * H_;
    float acc = 0.f, cum = 0.f;
    for (int s = 0; s < S_; s++) {
        float o = __ldg(ob + (size_t)s * H_ + t);
        acc = fmaf(e_s[s], o, acc);
        float ao = acc * dinv[s];
        size_t base = ((size_t)b * S_ + s) * IN_;
        __nv_bfloat16 ch = __float2bfloat16(cum);
        g_finH[base + t] = ch;
        g_finL[base + t] = __float2bfloat16(cum - __bfloat162float(ch));
        __nv_bfloat16 oh = __float2bfloat16(o);
        g_finH[base + H_ + t] = oh;
        g_finL[base + H_ + t] = __float2bfloat16(o - __bfloat162float(oh));
        cum += ao;
    }
}

// ---------------------------------------------------------------------------
// fc GEMM on HMMA (mma.sync bf16, hi/lo split, 3 terms)
#define FC_STAGE 65536
#define FC_SMEM (2 * FC_STAGE + 1024)

__global__ void __launch_bounds__(256, 1)
fcgemm_kernel(float* __restrict__ res) {
    extern __shared__ char dsm[];
    __shared__ float fcb_s[128];
    uint32_t sb = (s2u(dsm) + 1023u) & ~1023u;

    int tid = threadIdx.x;
    int wid = tid >> 5, lane = tid & 31;
    int ntile = blockIdx.x, mtile = blockIdx.y;
    size_t mBase = (size_t)mtile * 128;
    int nBase = ntile * 128;

    if (tid < 128) fcb_s[tid] = g_fcb[nBase + tid];

    const __nv_bfloat16* srcs[4] = {
        g_finH + mBase * IN_, g_finL + mBase * IN_,
        g_fwH + (size_t)nBase * IN_, g_fwL + (size_t)nBase * IN_ };

    auto stage = [&](int c) {
        uint32_t base = sb + (uint32_t)(c & 1) * FC_STAGE;
        int k0 = c * 64;
#pragma unroll
        for (int i = 0; i < 16; i++) {
            int idx = tid + 256 * i;
            int tile = idx >> 10;
            int w = idx & 1023;
            int rr = w >> 3, gg = w & 7;
            uint32_t dst = base + tile * 16384 + SWZ(w * 16);
            const __nv_bfloat16* src = srcs[tile] + (size_t)rr * IN_ + k0 + gg * 8;
            cpa16(dst, src);
        }
        CPA_COMMIT();
    };

    const int mrow0 = (wid & 1) * 64;
    const int ncol0 = (wid >> 1) * 32;

    float acc[4][4][4];
#pragma unroll
    for (int mi = 0; mi < 4; mi++)
#pragma unroll
        for (int nj = 0; nj < 4; nj++)
#pragma unroll
            for (int q = 0; q < 4; q++) acc[mi][nj][q] = 0.f;

    stage(0);
    stage(1);

    for (int c = 0; c < 8; c++) {
        if (c < 7) cpa_wait<1>(); else cpa_wait<0>();
        __syncthreads();
        uint32_t base = sb + (uint32_t)(c & 1) * FC_STAGE;

#pragma unroll
        for (int ks = 0; ks < 4; ks++) {
            int kw = ks * 16 + ((lane >> 4) << 3);
            uint32_t a_h[4][4], a_l[4][4];
#pragma unroll
            for (int mi = 0; mi < 4; mi++) {
                int row = mrow0 + mi * 16 + (lane & 15);
                uint32_t off = SWZ((uint32_t)(row * 128 + kw * 2));
                ldsm4(a_h[mi], base + off);
                ldsm4(a_l[mi], base + 16384 + off);
            }
            uint32_t b_h[2][4], b_l[2][4];
#pragma unroll
            for (int bj = 0; bj < 2; bj++) {
                int nrow = ncol0 + bj * 16 + (lane & 15);
                uint32_t off = SWZ((uint32_t)(nrow * 128 + kw * 2));
                ldsm4(b_h[bj], base + 32768 + off);
                ldsm4(b_l[bj], base + 49152 + off);
            }
#pragma unroll
            for (int mi = 0; mi < 4; mi++)
#pragma unroll
                for (int nj = 0; nj < 4; nj++) {
                    int bj = nj >> 1, sel = nj & 1;
                    mma16816(acc[mi][nj], a_h[mi], b_h[bj][sel], b_h[bj][sel + 2]);
                    mma16816(acc[mi][nj], a_l[mi], b_h[bj][sel], b_h[bj][sel + 2]);
                    mma16816(acc[mi][nj], a_h[mi], b_l[bj][sel], b_l[bj][sel + 2]);
                }
        }
        __syncthreads();
        if (c + 2 < 8) stage(c + 2);
    }

#pragma unroll
    for (int mi = 0; mi < 4; mi++) {
        int r0 = (int)mBase + mrow0 + mi * 16 + (lane >> 2);
#pragma unroll
        for (int nj = 0; nj < 4; nj++) {
            int lc = ncol0 + nj * 8 + (lane & 3) * 2;
            int col = nBase + lc;
            if (col < NC) {
                float b0 = fcb_s[lc], b1 = fcb_s[lc + 1];
                float2 v0 = make_float2(fsig(acc[mi][nj][0] + b0),
                                        fsig(acc[mi][nj][1] + b1));
                float2 v1 = make_float2(fsig(acc[mi][nj][2] + b0),
                                        fsig(acc[mi][nj][3] + b1));
                *reinterpret_cast<float2*>(res + (size_t)r0 * NC + col) = v0;
                *reinterpret_cast<float2*>(res + (size_t)(r0 + 8) * NC + col) = v1;
            }
        }
    }
}

// ---------------------------------------------------------------------------
extern "C" void kernel_launch(void* const* d_in, const int* in_sizes, int n_in,
                              void* d_out, int out_size) {
    const int*   skill      = (const int*)  d_in[0];
    const int*   answer     = (const int*)  d_in[1];
    const float* skill_emb  = (const float*)d_in[2];
    const float* answer_emb = (const float*)d_in[3];
    const float* Wih        = (const float*)d_in[4];
    const float* Whh        = (const float*)d_in[5];
    const float* bih        = (const float*)d_in[6];
    const float* bhh        = (const float*)d_in[7];
    const float* mlp_W      = (const float*)d_in[8];
    const float* mlp_b      = (const float*)d_in[9];
    const float* sim_W      = (const float*)d_in[10];
    const float* fc_W       = (const float*)d_in[11];
    const float* fc_b       = (const float*)d_in[12];

    float* res = (float*)d_out;
    float* sa  = (float*)d_out + RES_ELEMS;

    float* P1_p;  cudaGetSymbolAddress((void**)&P1_p,  g_P1);
    float* P0_p;  cudaGetSymbolAddress((void**)&P0_p,  g_P0);
    float* qb_p;  cudaGetSymbolAddress((void**)&qb_p,  g_qb);
    float* out_p; cudaGetSymbolAddress((void**)&out_p, g_out);
    float* t80_p; cudaGetSymbolAddress((void**)&t80_p, g_tmp80);

    cudaFuncSetAttribute(lstm_kernel,
                         cudaFuncAttributeMaxDynamicSharedMemorySize, LSTM_SMEM);
    cudaFuncSetAttribute(fcgemm_kernel,
                         cudaFuncAttributeMaxDynamicSharedMemorySize, FC_SMEM);

    qbias_kernel<<<8, 256>>>(Wih, answer_emb, bih, bhh);
    embed_kernel<<<MTOT, 256>>>(skill, answer, skill_emb, answer_emb, sa);
    convw_kernel<<<(1024 * IN_ + 255) / 256, 256>>>(fc_W, fc_b);

    {
        dim3 grid(G4 / 64, (1000 + 63) / 64);
        gemm_kernel<<<grid, 256>>>(skill_emb, H_, Wih,      IN_, qb_p + G4, P1_p,
                                   1000, G4, H_, 0);
        gemm_kernel<<<grid, 256>>>(skill_emb, H_, Wih + H_, IN_, qb_p,      P0_p,
                                   1000, G4, H_, 0);
    }

    lstm_kernel<<<128, 256, LSTM_SMEM>>>(skill, answer, Whh, out_p);

    {
        dim3 grid((AD + 63) / 64, MTOT / 64);
        gemm_kernel<<<grid, 256>>>(out_p, H_, mlp_W, H_, mlp_b, t80_p,
                                   MTOT, AD, H_, 1);
    }

    attdot_kernel<<<(MTOT * 32 + 255) / 256, 256>>>(sim_W);
    attnscan_kernel<<<B_, H_>>>();

    {
        dim3 grid(8, 256);   // ntile, mtile
        fcgemm_kernel<<<grid, 256, FC_SMEM>>>(res);
    }
}

// round 7
// speedup vs baseline: 10.3408x; 1.2116x over previous
#include <cuda_runtime.h>
#include <cuda_bf16.h>
#include <math.h>
#include <stdint.h>

#define B_    64
#define S_    512
#define H_    256
#define IN_   512
#define G4    1024      // 4*H
#define NC    1000
#define AD    80
#define MTOT  (B_*S_)   // 32768
#define RES_ELEMS (MTOT*NC)

// ---------------- scratch (device globals) ---------------------------------
__device__ float g_P1[1000 * G4];
__device__ float g_P0[1000 * G4];
__device__ float g_qb[2 * G4];
__device__ float g_out  [MTOT * H_];
__device__ float g_tmp80[MTOT * AD];
__device__ float g_att  [MTOT];
__device__ __nv_bfloat16 g_finH[MTOT * IN_];   // bf16 hi of [attn_cum_1 | out]
__device__ __nv_bfloat16 g_finL[MTOT * IN_];   // bf16 lo residual
__device__ __nv_bfloat16 g_fwH[1024 * IN_];    // fc_W hi (padded to 1024 rows)
__device__ __nv_bfloat16 g_fwL[1024 * IN_];    // fc_W lo
__device__ float g_fcb[1024];                  // fc_b padded

// ---------------- helpers ---------------------------------------------------
__device__ __forceinline__ unsigned long long fma2(unsigned long long a,
                                                   unsigned long long b,
                                                   unsigned long long c) {
    unsigned long long d;
    asm("fma.rn.f32x2 %0, %1, %2, %3;" : "=l"(d) : "l"(a), "l"(b), "l"(c));
    return d;
}
__device__ __forceinline__ float f2sum(unsigned long long v) {
    float lo, hi;
    asm("mov.b64 {%0, %1}, %2;" : "=f"(lo), "=f"(hi) : "l"(v));
    return lo + hi;
}
__device__ __forceinline__ uint32_t s2u(const void* p) {
    uint32_t a;
    asm("{ .reg .u64 t; cvta.to.shared.u64 t, %1; cvt.u32.u64 %0, t; }"
        : "=r"(a) : "l"(p));
    return a;
}
// fast activations (MUFU-based)
__device__ __forceinline__ float fsig(float x) {
    return __fdividef(1.0f, 1.0f + __expf(-x));
}
__device__ __forceinline__ float ftanh(float x) {
    return __fdividef(2.0f, 1.0f + __expf(-2.0f * x)) - 1.0f;
}

#define SWZ(o) ((o) ^ (((o) >> 3) & 0x70))

__device__ __forceinline__ void cpa16(uint32_t dst, const void* src) {
    asm volatile("cp.async.cg.shared.global [%0], [%1], 16;" :: "r"(dst), "l"(src) : "memory");
}
#define CPA_COMMIT() asm volatile("cp.async.commit_group;" ::: "memory")
template<int N> __device__ __forceinline__ void cpa_wait() {
    asm volatile("cp.async.wait_group %0;" :: "n"(N) : "memory");
}

__device__ __forceinline__ void ldsm4(uint32_t (&r)[4], uint32_t addr) {
    asm volatile("ldmatrix.sync.aligned.m8n8.x4.shared.b16 {%0,%1,%2,%3}, [%4];"
        : "=r"(r[0]), "=r"(r[1]), "=r"(r[2]), "=r"(r[3]) : "r"(addr));
}
__device__ __forceinline__ void mma16816(float (&d)[4], const uint32_t (&a)[4],
                                         uint32_t b0, uint32_t b1) {
    asm volatile("mma.sync.aligned.m16n8k16.row.col.f32.bf16.bf16.f32 "
        "{%0,%1,%2,%3}, {%4,%5,%6,%7}, {%8,%9}, {%0,%1,%2,%3};"
        : "+f"(d[0]), "+f"(d[1]), "+f"(d[2]), "+f"(d[3])
        : "r"(a[0]), "r"(a[1]), "r"(a[2]), "r"(a[3]), "r"(b0), "r"(b1));
}

// mbarrier primitives
#define MBAR_INIT(a, cnt) asm volatile("mbarrier.init.shared.b64 [%0], %1;" :: "r"(a), "r"(cnt) : "memory")
#define MBAR_EXPECT(a, bytes) asm volatile("mbarrier.arrive.expect_tx.shared.b64 _, [%0], %1;" :: "r"(a), "r"(bytes) : "memory")
__device__ __forceinline__ void mbar_wait_cluster(uint32_t mbar, uint32_t parity) {
    uint32_t done;
    asm volatile(
        "{\n\t.reg .pred p;\n\t"
        "mbarrier.try_wait.parity.acquire.cluster.shared::cta.b64 p, [%1], %2;\n\t"
        "selp.b32 %0, 1, 0, p;\n\t}"
        : "=r"(done) : "r"(mbar), "r"(parity) : "memory");
    if (!done) {
        asm volatile(
            "{\n\t.reg .pred P1;\n\t"
            "WL_%=:\n\t"
            "mbarrier.try_wait.parity.acquire.cluster.shared::cta.b64 P1, [%0], %1, 0x989680;\n\t"
            "@P1 bra.uni WD_%=;\n\t"
            "bra.uni WL_%=;\n\t"
            "WD_%=:\n\t}"
            :: "r"(mbar), "r"(parity) : "memory");
    }
}
__device__ __forceinline__ void st_async_u32(uint32_t addr, uint32_t val, uint32_t mbar) {
    asm volatile("st.async.shared::cluster.mbarrier::complete_tx::bytes.b32 [%0], %1, [%2];"
                 :: "r"(addr), "r"(val), "r"(mbar) : "memory");
}

// ---------------------------------------------------------------------------
__global__ void qbias_kernel(const float* __restrict__ Wih,
                             const float* __restrict__ answer_emb,
                             const float* __restrict__ bih,
                             const float* __restrict__ bhh) {
    int idx = blockIdx.x * blockDim.x + threadIdx.x;
    if (idx >= 2 * G4) return;
    int a = idx >> 10;
    int row = idx & (G4 - 1);
    int off = (a == 1) ? H_ : 0;
    float s = bih[row] + bhh[row];
    const float* wr = Wih + (size_t)row * IN_ + off;
    const float* ar = answer_emb + a * H_;
#pragma unroll 4
    for (int k = 0; k < H_; k++) s += wr[k] * ar[k];
    g_qb[idx] = s;
}

// ---------------------------------------------------------------------------
__global__ void embed_kernel(const int* __restrict__ skill,
                             const int* __restrict__ answer,
                             const float* __restrict__ skill_emb,
                             const float* __restrict__ answer_emb,
                             float* __restrict__ sa) {
    int r = blockIdx.x;
    int t = threadIdx.x;
    int sk = skill[r];
    int an = answer[r];
    float se = skill_emb[sk * H_ + t];
    float ae = answer_emb[an * H_ + t];
    float* o = sa + (size_t)r * IN_;
    if (an == 1) { o[t] = se; o[H_ + t] = ae; }
    else         { o[t] = ae; o[H_ + t] = se; }
}

// ---------------------------------------------------------------------------
__global__ void convw_kernel(const float* __restrict__ fc_W,
                             const float* __restrict__ fc_b) {
    int idx = blockIdx.x * blockDim.x + threadIdx.x;
    if (idx >= 1024 * IN_) return;
    int row = idx >> 9;
    float x = (row < NC) ? fc_W[(size_t)row * IN_ + (idx & 511)] : 0.f;
    __nv_bfloat16 h = __float2bfloat16(x);
    g_fwH[idx] = h;
    g_fwL[idx] = __float2bfloat16(x - __bfloat162float(h));
    if (idx < 1024) g_fcb[idx] = (idx < NC) ? fc_b[idx] : 0.f;
}

// ---------------------------------------------------------------------------
// fp32 GEMM (f32x2) — P tables and mlp
__global__ void gemm_kernel(const float* __restrict__ A, int lda,
                            const float* __restrict__ Bm, int ldb,
                            const float* __restrict__ bias,
                            float* __restrict__ C,
                            int M, int N, int K, int act) {
    __shared__ float2 As2[8][64];
    __shared__ float2 Bs2[8][64];

    int tid = threadIdx.x;
    int tx = tid & 15;
    int ty = tid >> 4;
    int rowBase = blockIdx.y * 64;
    int colBase = blockIdx.x * 64;
    int ldRow = tid >> 2;
    int ldCol = (tid & 3) * 4;

    unsigned long long acc[4][4];
#pragma unroll
    for (int i = 0; i < 4; i++)
#pragma unroll
        for (int j = 0; j < 4; j++) acc[i][j] = 0ULL;

    for (int k0 = 0; k0 < K; k0 += 16) {
        int arow = rowBase + ldRow; if (arow > M - 1) arow = M - 1;
        float4 av = *reinterpret_cast<const float4*>(A + (size_t)arow * lda + k0 + ldCol);
        As2[ldCol / 2][ldRow]     = make_float2(av.x, av.y);
        As2[ldCol / 2 + 1][ldRow] = make_float2(av.z, av.w);
        int n = colBase + ldRow;
        float4 bv = make_float4(0.f, 0.f, 0.f, 0.f);
        if (n < N)
            bv = *reinterpret_cast<const float4*>(Bm + (size_t)n * ldb + k0 + ldCol);
        Bs2[ldCol / 2][ldRow]     = make_float2(bv.x, bv.y);
        Bs2[ldCol / 2 + 1][ldRow] = make_float2(bv.z, bv.w);
        __syncthreads();

#pragma unroll
        for (int kk2 = 0; kk2 < 8; kk2++) {
            ulonglong2 aA = *reinterpret_cast<const ulonglong2*>(&As2[kk2][ty * 4]);
            ulonglong2 aB = *reinterpret_cast<const ulonglong2*>(&As2[kk2][ty * 4 + 2]);
            unsigned long long a2[4] = {aA.x, aA.y, aB.x, aB.y};
            unsigned long long b2[4];
#pragma unroll
            for (int j = 0; j < 4; j++)
                b2[j] = *reinterpret_cast<const unsigned long long*>(&Bs2[kk2][tx + 16 * j]);
#pragma unroll
            for (int i = 0; i < 4; i++)
#pragma unroll
                for (int j = 0; j < 4; j++)
                    acc[i][j] = fma2(a2[i], b2[j], acc[i][j]);
        }
        __syncthreads();
    }

#pragma unroll
    for (int i = 0; i < 4; i++) {
        int row = rowBase + ty * 4 + i;
        if (row >= M) continue;
#pragma unroll
        for (int j = 0; j < 4; j++) {
            int col = colBase + tx + 16 * j;
            if (col < N) {
                float v = f2sum(acc[i][j]);
                if (bias) v += bias[col];
                if (act == 1) v = ftanh(v);
                else if (act == 2) v = fsig(v);
                C[(size_t)row * N + col] = v;
            }
        }
    }
}

// ---------------------------------------------------------------------------
// LSTM v4: register weights + mbarrier/st.async h exchange (no cluster barrier
// in the loop). 16 clusters x 8 CTAs x 4 batches.
// h for step t lives in buffer[t&1], signaled on mbar[t&1] with 4096 tx bytes.
#define LSTM_SMEM ((8 + 2*4*H_ + 8*4*4*32 + 128 + 2*4*S_) * 4)

__global__ void __cluster_dims__(8, 1, 1) __launch_bounds__(256, 1)
lstm_kernel(const int* __restrict__ skill, const int* __restrict__ answer,
            const float* __restrict__ Whh, float* __restrict__ out) {
    extern __shared__ float smem[];
    // [0..4): mbar[2] (2 x u64), then h, gp, c, indices
    float* mb_f = smem;                  // 2 u64 mbarriers (16B)
    float* h_s  = smem + 8;              // [2][4][256]
    float* gp   = h_s + 2 * 4 * H_;      // [8 w][4 g][4 b][32 l]
    float* c_s  = gp + 8 * 4 * 4 * 32;   // [128]
    int* sk_s   = (int*)(c_s + 128);     // [4][512]
    int* an_s   = sk_s + 4 * S_;         // [4][512]

    int tid  = threadIdx.x;
    int w    = tid >> 5;
    int l    = tid & 31;
    int rank = blockIdx.x & 7;
    int cid  = blockIdx.x >> 3;

    uint32_t mbar_u32[2];
    mbar_u32[0] = s2u(mb_f);
    mbar_u32[1] = s2u(mb_f) + 8;

    // weights -> registers (one-time)
    float2 wreg[4][16];
#pragma unroll
    for (int g = 0; g < 4; g++) {
        const float* rowp = Whh + (size_t)(g * H_ + rank * 32 + l) * H_ + w * 32;
#pragma unroll
        for (int j = 0; j < 16; j++)
            wreg[g][j] = *reinterpret_cast<const float2*>(rowp + j * 2);
    }

    for (int i = tid; i < 4 * H_; i += 256) h_s[i] = 0.f;   // buffer 0
    if (tid < 128) c_s[tid] = 0.f;
    for (int i = tid; i < 4 * S_; i += 256) {
        int bb = i >> 9, ss = i & (S_ - 1);
        int ridx = (cid * 4 + bb) * S_ + ss;
        sk_s[i] = skill[ridx];
        an_s[i] = answer[ridx];
    }
    if (tid == 0) {
        MBAR_INIT(mbar_u32[0], 1);
        MBAR_INIT(mbar_u32[1], 1);
    }
    __syncthreads();
    asm volatile("barrier.cluster.arrive.aligned;" ::: "memory");
    asm volatile("barrier.cluster.wait.aligned;" ::: "memory");

    const int uu  = tid & 31;
    const int ubb = tid >> 5;            // valid for tid<128
    uint32_t h_s_u32 = s2u(h_s);

    // hoisted remote addresses (2 buffers x 8 ranks) + mbar deltas
    uint32_t radr[2][8];
    uint32_t mdel[2];
    if (tid < 128) {
        uint32_t off0 = h_s_u32 + (ubb * H_ + 32 * rank + uu) * 4;
#pragma unroll
        for (int c8 = 0; c8 < 8; c8++) {
            asm("mapa.shared::cluster.u32 %0, %1, %2;"
                : "=r"(radr[0][c8]) : "r"(off0), "r"(c8));
            asm("mapa.shared::cluster.u32 %0, %1, %2;"
                : "=r"(radr[1][c8]) : "r"(off0 + 4 * H_ * 4), "r"(c8));
        }
        mdel[0] = mbar_u32[0] - off0;                   // mbar[0] rel to buf0 slot
        mdel[1] = mbar_u32[1] - (off0 + 4 * H_ * 4);    // mbar[1] rel to buf1 slot
    }

    int ph[2] = {0, 0};

    for (int s = 0; s < S_; s++) {
        const int p = s & 1;
        const int q = p ^ 1;          // buffer/mbar for step s+1 data

        // post expected tx for next step's h (4096 bytes = 8 CTAs x 512B)
        if (tid == 0) MBAR_EXPECT(mbar_u32[q], 4096);

        // wait for this step's h (skip step 0: zeros prefilled)
        if (s > 0) {
            mbar_wait_cluster(mbar_u32[p], ph[p]);
            ph[p] ^= 1;
        }

        const float* hb = h_s + p * 4 * H_ + w * 32;

        // prefetch P rows for update phase
        float pv[4] = {0.f, 0.f, 0.f, 0.f};
        if (tid < 128) {
            int sk = sk_s[ubb * S_ + s];
            int an = an_s[ubb * S_ + s];
            const float* P = an ? g_P1 : g_P0;
            const float* Pb = P + (size_t)sk * G4 + 32 * rank + uu;
            pv[0] = __ldg(Pb);
            pv[1] = __ldg(Pb + H_);
            pv[2] = __ldg(Pb + 2 * H_);
            pv[3] = __ldg(Pb + 3 * H_);
        }

        // fma over this warp's k-slice (broadcast h loads, register weights)
        unsigned long long acc[4][4];
#pragma unroll
        for (int g = 0; g < 4; g++)
#pragma unroll
            for (int b = 0; b < 4; b++) acc[g][b] = 0ULL;

#pragma unroll
        for (int k4 = 0; k4 < 8; k4++) {
            ulonglong2 hv[4];
#pragma unroll
            for (int b = 0; b < 4; b++)
                hv[b] = *reinterpret_cast<const ulonglong2*>(hb + b * H_ + k4 * 4);
#pragma unroll
            for (int g = 0; g < 4; g++) {
                unsigned long long w0 =
                    *reinterpret_cast<const unsigned long long*>(&wreg[g][k4 * 2]);
                unsigned long long w1 =
                    *reinterpret_cast<const unsigned long long*>(&wreg[g][k4 * 2 + 1]);
#pragma unroll
                for (int b = 0; b < 4; b++) {
                    acc[g][b] = fma2(w0, hv[b].x, acc[g][b]);
                    acc[g][b] = fma2(w1, hv[b].y, acc[g][b]);
                }
            }
        }
#pragma unroll
        for (int g = 0; g < 4; g++)
#pragma unroll
            for (int b = 0; b < 4; b++)
                gp[((w * 4 + g) * 4 + b) * 32 + l] = f2sum(acc[g][b]);
        __syncthreads();

        if (tid < 128) {
            float v[4];
#pragma unroll
            for (int g = 0; g < 4; g++) {
                float sum = pv[g];
#pragma unroll
                for (int ww = 0; ww < 8; ww++)
                    sum += gp[((ww * 4 + g) * 4 + ubb) * 32 + uu];
                v[g] = sum;
            }
            float ig = fsig(v[0]), fg = fsig(v[1]);
            float gg = ftanh(v[2]), og = fsig(v[3]);
            float c = fg * c_s[tid] + ig * gg;
            c_s[tid] = c;
            float h = og * ftanh(c);
            int b = cid * 4 + ubb;
            out[(size_t)b * S_ * H_ + (size_t)s * H_ + 32 * rank + uu] = h;
            uint32_t hbits = __float_as_uint(h);
            const uint32_t* ra = radr[q];
            uint32_t md = mdel[q];
#pragma unroll
            for (int c8 = 0; c8 < 8; c8++)
                st_async_u32(ra[c8], hbits, ra[c8] + md);
        }
        // no cluster barrier: next iteration's mbar wait provides the sync
    }

    // drain: wait for step-512 completions so peers' stores to us (and ours to
    // them, via their waits) have landed before smem is torn down.
    mbar_wait_cluster(mbar_u32[0], ph[0]);
}

// ---------------------------------------------------------------------------
__global__ void attdot_kernel(const float* __restrict__ simW) {
    int warp = (blockIdx.x * blockDim.x + threadIdx.x) >> 5;
    int lane = threadIdx.x & 31;
    if (warp >= MTOT) return;
    const float* rowp = g_tmp80 + (size_t)warp * AD;
    float v = rowp[lane] * simW[lane] + rowp[lane + 32] * simW[lane + 32];
    if (lane < 16) v += rowp[lane + 64] * simW[lane + 64];
#pragma unroll
    for (int off = 16; off > 0; off >>= 1)
        v += __shfl_down_sync(0xFFFFFFFFu, v, off);
    if (lane == 0) g_att[warp] = v;
}

// ---------------------------------------------------------------------------
// prefix-softmax attention; emits final = [attn_cum_1 | out] as bf16 hi/lo
__global__ void attnscan_kernel() {
    int b = blockIdx.x;
    int t = threadIdx.x;
    __shared__ float e_s[S_];
    __shared__ float dinv[S_];
    for (int s = t; s < S_; s += H_) e_s[s] = __expf(g_att[b * S_ + s]);
    __syncthreads();
    if (t == 0) {
        float run = 0.f;
        for (int s = 0; s < S_; s++) { run += e_s[s]; dinv[s] = __fdividef(1.0f, run); }
    }
    __syncthreads();

    const float* ob = g_out + (size_t)b * S_ * H_;
    float acc = 0.f, cum = 0.f;
    for (int s = 0; s < S_; s++) {
        float o = __ldg(ob + (size_t)s * H_ + t);
        acc = fmaf(e_s[s], o, acc);
        float ao = acc * dinv[s];
        size_t base = ((size_t)b * S_ + s) * IN_;
        __nv_bfloat16 ch = __float2bfloat16(cum);
        g_finH[base + t] = ch;
        g_finL[base + t] = __float2bfloat16(cum - __bfloat162float(ch));
        __nv_bfloat16 oh = __float2bfloat16(o);
        g_finH[base + H_ + t] = oh;
        g_finL[base + H_ + t] = __float2bfloat16(o - __bfloat162float(oh));
        cum += ao;
    }
}

// ---------------------------------------------------------------------------
// fc GEMM on HMMA (mma.sync bf16, hi/lo split, 3 terms)
#define FC_STAGE 65536
#define FC_SMEM (2 * FC_STAGE + 1024)

__global__ void __launch_bounds__(256, 1)
fcgemm_kernel(float* __restrict__ res) {
    extern __shared__ char dsm[];
    __shared__ float fcb_s[128];
    uint32_t sb = (s2u(dsm) + 1023u) & ~1023u;

    int tid = threadIdx.x;
    int wid = tid >> 5, lane = tid & 31;
    int ntile = blockIdx.x, mtile = blockIdx.y;
    size_t mBase = (size_t)mtile * 128;
    int nBase = ntile * 128;

    if (tid < 128) fcb_s[tid] = g_fcb[nBase + tid];

    const __nv_bfloat16* srcs[4] = {
        g_finH + mBase * IN_, g_finL + mBase * IN_,
        g_fwH + (size_t)nBase * IN_, g_fwL + (size_t)nBase * IN_ };

    auto stage = [&](int c) {
        uint32_t base = sb + (uint32_t)(c & 1) * FC_STAGE;
        int k0 = c * 64;
#pragma unroll
        for (int i = 0; i < 16; i++) {
            int idx = tid + 256 * i;
            int tile = idx >> 10;
            int w = idx & 1023;
            int rr = w >> 3, gg = w & 7;
            uint32_t dst = base + tile * 16384 + SWZ(w * 16);
            const __nv_bfloat16* src = srcs[tile] + (size_t)rr * IN_ + k0 + gg * 8;
            cpa16(dst, src);
        }
        CPA_COMMIT();
    };

    const int mrow0 = (wid & 1) * 64;
    const int ncol0 = (wid >> 1) * 32;

    float acc[4][4][4];
#pragma unroll
    for (int mi = 0; mi < 4; mi++)
#pragma unroll
        for (int nj = 0; nj < 4; nj++)
#pragma unroll
            for (int q = 0; q < 4; q++) acc[mi][nj][q] = 0.f;

    stage(0);
    stage(1);

    for (int c = 0; c < 8; c++) {
        if (c < 7) cpa_wait<1>(); else cpa_wait<0>();
        __syncthreads();
        uint32_t base = sb + (uint32_t)(c & 1) * FC_STAGE;

#pragma unroll
        for (int ks = 0; ks < 4; ks++) {
            int kw = ks * 16 + ((lane >> 4) << 3);
            uint32_t a_h[4][4], a_l[4][4];
#pragma unroll
            for (int mi = 0; mi < 4; mi++) {
                int row = mrow0 + mi * 16 + (lane & 15);
                uint32_t off = SWZ((uint32_t)(row * 128 + kw * 2));
                ldsm4(a_h[mi], base + off);
                ldsm4(a_l[mi], base + 16384 + off);
            }
            uint32_t b_h[2][4], b_l[2][4];
#pragma unroll
            for (int bj = 0; bj < 2; bj++) {
                int nrow = ncol0 + bj * 16 + (lane & 15);
                uint32_t off = SWZ((uint32_t)(nrow * 128 + kw * 2));
                ldsm4(b_h[bj], base + 32768 + off);
                ldsm4(b_l[bj], base + 49152 + off);
            }
#pragma unroll
            for (int mi = 0; mi < 4; mi++)
#pragma unroll
                for (int nj = 0; nj < 4; nj++) {
                    int bj = nj >> 1, sel = nj & 1;
                    mma16816(acc[mi][nj], a_h[mi], b_h[bj][sel], b_h[bj][sel + 2]);
                    mma16816(acc[mi][nj], a_l[mi], b_h[bj][sel], b_h[bj][sel + 2]);
                    mma16816(acc[mi][nj], a_h[mi], b_l[bj][sel], b_l[bj][sel + 2]);
                }
        }
        __syncthreads();
        if (c + 2 < 8) stage(c + 2);
    }

#pragma unroll
    for (int mi = 0; mi < 4; mi++) {
        int r0 = (int)mBase + mrow0 + mi * 16 + (lane >> 2);
#pragma unroll
        for (int nj = 0; nj < 4; nj++) {
            int lc = ncol0 + nj * 8 + (lane & 3) * 2;
            int col = nBase + lc;
            if (col < NC) {
                float b0 = fcb_s[lc], b1 = fcb_s[lc + 1];
                float2 v0 = make_float2(fsig(acc[mi][nj][0] + b0),
                                        fsig(acc[mi][nj][1] + b1));
                float2 v1 = make_float2(fsig(acc[mi][nj][2] + b0),
                                        fsig(acc[mi][nj][3] + b1));
                *reinterpret_cast<float2*>(res + (size_t)r0 * NC + col) = v0;
                *reinterpret_cast<float2*>(res + (size_t)(r0 + 8) * NC + col) = v1;
            }
        }
    }
}

// ---------------------------------------------------------------------------
extern "C" void kernel_launch(void* const* d_in, const int* in_sizes, int n_in,
                              void* d_out, int out_size) {
    const int*   skill      = (const int*)  d_in[0];
    const int*   answer     = (const int*)  d_in[1];
    const float* skill_emb  = (const float*)d_in[2];
    const float* answer_emb = (const float*)d_in[3];
    const float* Wih        = (const float*)d_in[4];
    const float* Whh        = (const float*)d_in[5];
    const float* bih        = (const float*)d_in[6];
    const float* bhh        = (const float*)d_in[7];
    const float* mlp_W      = (const float*)d_in[8];
    const float* mlp_b      = (const float*)d_in[9];
    const float* sim_W      = (const float*)d_in[10];
    const float* fc_W       = (const float*)d_in[11];
    const float* fc_b       = (const float*)d_in[12];

    float* res = (float*)d_out;
    float* sa  = (float*)d_out + RES_ELEMS;

    float* P1_p;  cudaGetSymbolAddress((void**)&P1_p,  g_P1);
    float* P0_p;  cudaGetSymbolAddress((void**)&P0_p,  g_P0);
    float* qb_p;  cudaGetSymbolAddress((void**)&qb_p,  g_qb);
    float* out_p; cudaGetSymbolAddress((void**)&out_p, g_out);
    float* t80_p; cudaGetSymbolAddress((void**)&t80_p, g_tmp80);

    cudaFuncSetAttribute(lstm_kernel,
                         cudaFuncAttributeMaxDynamicSharedMemorySize, LSTM_SMEM);
    cudaFuncSetAttribute(fcgemm_kernel,
                         cudaFuncAttributeMaxDynamicSharedMemorySize, FC_SMEM);

    qbias_kernel<<<8, 256>>>(Wih, answer_emb, bih, bhh);
    embed_kernel<<<MTOT, 256>>>(skill, answer, skill_emb, answer_emb, sa);
    convw_kernel<<<(1024 * IN_ + 255) / 256, 256>>>(fc_W, fc_b);

    {
        dim3 grid(G4 / 64, (1000 + 63) / 64);
        gemm_kernel<<<grid, 256>>>(skill_emb, H_, Wih,      IN_, qb_p + G4, P1_p,
                                   1000, G4, H_, 0);
        gemm_kernel<<<grid, 256>>>(skill_emb, H_, Wih + H_, IN_, qb_p,      P0_p,
                                   1000, G4, H_, 0);
    }

    lstm_kernel<<<128, 256, LSTM_SMEM>>>(skill, answer, Whh, out_p);

    {
        dim3 grid((AD + 63) / 64, MTOT / 64);
        gemm_kernel<<<grid, 256>>>(out_p, H_, mlp_W, H_, mlp_b, t80_p,
                                   MTOT, AD, H_, 1);
    }

    attdot_kernel<<<(MTOT * 32 + 255) / 256, 256>>>(sim_W);
    attnscan_kernel<<<B_, H_>>>();

    {
        dim3 grid(8, 256);   // ntile, mtile
        fcgemm_kernel<<<grid, 256, FC_SMEM>>>(res);
    }
}

// round 8
// speedup vs baseline: 11.1597x; 1.0792x over previous
#include <cuda_runtime.h>
#include <cuda_bf16.h>
#include <math.h>
#include <stdint.h>

#define B_    64
#define S_    512
#define H_    256
#define IN_   512
#define G4    1024      // 4*H
#define NC    1000
#define AD    80
#define MTOT  (B_*S_)   // 32768
#define RES_ELEMS (MTOT*NC)

// ---------------- scratch (device globals) ---------------------------------
__device__ float g_P1[1000 * G4];
__device__ float g_P0[1000 * G4];
__device__ float g_qb[2 * G4];
__device__ float g_out  [MTOT * H_];
__device__ float g_tmp80[MTOT * AD];
__device__ float g_att  [MTOT];
__device__ __nv_bfloat16 g_finH[MTOT * IN_];   // bf16 hi of [attn_cum_1 | out]
__device__ __nv_bfloat16 g_finL[MTOT * IN_];   // bf16 lo residual
__device__ __nv_bfloat16 g_fwH[1024 * IN_];    // fc_W hi (padded to 1024 rows)
__device__ __nv_bfloat16 g_fwL[1024 * IN_];    // fc_W lo
__device__ float g_fcb[1024];                  // fc_b padded

// ---------------- helpers ---------------------------------------------------
__device__ __forceinline__ unsigned long long fma2(unsigned long long a,
                                                   unsigned long long b,
                                                   unsigned long long c) {
    unsigned long long d;
    asm("fma.rn.f32x2 %0, %1, %2, %3;" : "=l"(d) : "l"(a), "l"(b), "l"(c));
    return d;
}
__device__ __forceinline__ float f2sum(unsigned long long v) {
    float lo, hi;
    asm("mov.b64 {%0, %1}, %2;" : "=f"(lo), "=f"(hi) : "l"(v));
    return lo + hi;
}
__device__ __forceinline__ uint32_t s2u(const void* p) {
    uint32_t a;
    asm("{ .reg .u64 t; cvta.to.shared.u64 t, %1; cvt.u32.u64 %0, t; }"
        : "=r"(a) : "l"(p));
    return a;
}
// fast activations (MUFU-based)
__device__ __forceinline__ float fsig(float x) {
    return __fdividef(1.0f, 1.0f + __expf(-x));
}
__device__ __forceinline__ float ftanh(float x) {
    return __fdividef(2.0f, 1.0f + __expf(-2.0f * x)) - 1.0f;
}

#define SWZ(o) ((o) ^ (((o) >> 3) & 0x70))

__device__ __forceinline__ void cpa16(uint32_t dst, const void* src) {
    asm volatile("cp.async.cg.shared.global [%0], [%1], 16;" :: "r"(dst), "l"(src) : "memory");
}
#define CPA_COMMIT() asm volatile("cp.async.commit_group;" ::: "memory")
template<int N> __device__ __forceinline__ void cpa_wait() {
    asm volatile("cp.async.wait_group %0;" :: "n"(N) : "memory");
}

__device__ __forceinline__ void ldsm4(uint32_t (&r)[4], uint32_t addr) {
    asm volatile("ldmatrix.sync.aligned.m8n8.x4.shared.b16 {%0,%1,%2,%3}, [%4];"
        : "=r"(r[0]), "=r"(r[1]), "=r"(r[2]), "=r"(r[3]) : "r"(addr));
}
__device__ __forceinline__ void mma16816(float (&d)[4], const uint32_t (&a)[4],
                                         uint32_t b0, uint32_t b1) {
    asm volatile("mma.sync.aligned.m16n8k16.row.col.f32.bf16.bf16.f32 "
        "{%0,%1,%2,%3}, {%4,%5,%6,%7}, {%8,%9}, {%0,%1,%2,%3};"
        : "+f"(d[0]), "+f"(d[1]), "+f"(d[2]), "+f"(d[3])
        : "r"(a[0]), "r"(a[1]), "r"(a[2]), "r"(a[3]), "r"(b0), "r"(b1));
}

// mbarrier primitives
#define MBAR_INIT(a, cnt) asm volatile("mbarrier.init.shared.b64 [%0], %1;" :: "r"(a), "r"(cnt) : "memory")
#define MBAR_EXPECT(a, bytes) asm volatile("mbarrier.arrive.expect_tx.shared.b64 _, [%0], %1;" :: "r"(a), "r"(bytes) : "memory")
__device__ __forceinline__ void mbar_wait_cluster(uint32_t mbar, uint32_t parity) {
    uint32_t done;
    asm volatile(
        "{\n\t.reg .pred p;\n\t"
        "mbarrier.try_wait.parity.acquire.cluster.shared::cta.b64 p, [%1], %2;\n\t"
        "selp.b32 %0, 1, 0, p;\n\t}"
        : "=r"(done) : "r"(mbar), "r"(parity) : "memory");
    if (!done) {
        asm volatile(
            "{\n\t.reg .pred P1;\n\t"
            "WL_%=:\n\t"
            "mbarrier.try_wait.parity.acquire.cluster.shared::cta.b64 P1, [%0], %1, 0x989680;\n\t"
            "@P1 bra.uni WD_%=;\n\t"
            "bra.uni WL_%=;\n\t"
            "WD_%=:\n\t}"
            :: "r"(mbar), "r"(parity) : "memory");
    }
}
__device__ __forceinline__ void st_async_u32(uint32_t addr, uint32_t val, uint32_t mbar) {
    asm volatile("st.async.shared::cluster.mbarrier::complete_tx::bytes.b32 [%0], %1, [%2];"
                 :: "r"(addr), "r"(val), "r"(mbar) : "memory");
}

// pack float2 -> bf16 hi pair + bf16 lo-residual pair
__device__ __forceinline__ void packhl(float2 v, uint32_t& hi, uint32_t& lo) {
    __nv_bfloat16 h0 = __float2bfloat16(v.x), h1 = __float2bfloat16(v.y);
    hi = ((uint32_t)__bfloat16_as_ushort(h1) << 16) | __bfloat16_as_ushort(h0);
    __nv_bfloat16 l0 = __float2bfloat16(v.x - __bfloat162float(h0));
    __nv_bfloat16 l1 = __float2bfloat16(v.y - __bfloat162float(h1));
    lo = ((uint32_t)__bfloat16_as_ushort(l1) << 16) | __bfloat16_as_ushort(l0);
}

// ---------------------------------------------------------------------------
__global__ void qbias_kernel(const float* __restrict__ Wih,
                             const float* __restrict__ answer_emb,
                             const float* __restrict__ bih,
                             const float* __restrict__ bhh) {
    int idx = blockIdx.x * blockDim.x + threadIdx.x;
    if (idx >= 2 * G4) return;
    int a = idx >> 10;
    int row = idx & (G4 - 1);
    int off = (a == 1) ? H_ : 0;
    float s = bih[row] + bhh[row];
    const float* wr = Wih + (size_t)row * IN_ + off;
    const float* ar = answer_emb + a * H_;
#pragma unroll 4
    for (int k = 0; k < H_; k++) s += wr[k] * ar[k];
    g_qb[idx] = s;
}

// ---------------------------------------------------------------------------
__global__ void embed_kernel(const int* __restrict__ skill,
                             const int* __restrict__ answer,
                             const float* __restrict__ skill_emb,
                             const float* __restrict__ answer_emb,
                             float* __restrict__ sa) {
    int r = blockIdx.x;
    int t = threadIdx.x;
    int sk = skill[r];
    int an = answer[r];
    float se = skill_emb[sk * H_ + t];
    float ae = answer_emb[an * H_ + t];
    float* o = sa + (size_t)r * IN_;
    if (an == 1) { o[t] = se; o[H_ + t] = ae; }
    else         { o[t] = ae; o[H_ + t] = se; }
}

// ---------------------------------------------------------------------------
__global__ void convw_kernel(const float* __restrict__ fc_W,
                             const float* __restrict__ fc_b) {
    int idx = blockIdx.x * blockDim.x + threadIdx.x;
    if (idx >= 1024 * IN_) return;
    int row = idx >> 9;
    float x = (row < NC) ? fc_W[(size_t)row * IN_ + (idx & 511)] : 0.f;
    __nv_bfloat16 h = __float2bfloat16(x);
    g_fwH[idx] = h;
    g_fwL[idx] = __float2bfloat16(x - __bfloat162float(h));
    if (idx < 1024) g_fcb[idx] = (idx < NC) ? fc_b[idx] : 0.f;
}

// ---------------------------------------------------------------------------
// fp32 GEMM (f32x2) — P tables and mlp
__global__ void gemm_kernel(const float* __restrict__ A, int lda,
                            const float* __restrict__ Bm, int ldb,
                            const float* __restrict__ bias,
                            float* __restrict__ C,
                            int M, int N, int K, int act) {
    __shared__ float2 As2[8][64];
    __shared__ float2 Bs2[8][64];

    int tid = threadIdx.x;
    int tx = tid & 15;
    int ty = tid >> 4;
    int rowBase = blockIdx.y * 64;
    int colBase = blockIdx.x * 64;
    int ldRow = tid >> 2;
    int ldCol = (tid & 3) * 4;

    unsigned long long acc[4][4];
#pragma unroll
    for (int i = 0; i < 4; i++)
#pragma unroll
        for (int j = 0; j < 4; j++) acc[i][j] = 0ULL;

    for (int k0 = 0; k0 < K; k0 += 16) {
        int arow = rowBase + ldRow; if (arow > M - 1) arow = M - 1;
        float4 av = *reinterpret_cast<const float4*>(A + (size_t)arow * lda + k0 + ldCol);
        As2[ldCol / 2][ldRow]     = make_float2(av.x, av.y);
        As2[ldCol / 2 + 1][ldRow] = make_float2(av.z, av.w);
        int n = colBase + ldRow;
        float4 bv = make_float4(0.f, 0.f, 0.f, 0.f);
        if (n < N)
            bv = *reinterpret_cast<const float4*>(Bm + (size_t)n * ldb + k0 + ldCol);
        Bs2[ldCol / 2][ldRow]     = make_float2(bv.x, bv.y);
        Bs2[ldCol / 2 + 1][ldRow] = make_float2(bv.z, bv.w);
        __syncthreads();

#pragma unroll
        for (int kk2 = 0; kk2 < 8; kk2++) {
            ulonglong2 aA = *reinterpret_cast<const ulonglong2*>(&As2[kk2][ty * 4]);
            ulonglong2 aB = *reinterpret_cast<const ulonglong2*>(&As2[kk2][ty * 4 + 2]);
            unsigned long long a2[4] = {aA.x, aA.y, aB.x, aB.y};
            unsigned long long b2[4];
#pragma unroll
            for (int j = 0; j < 4; j++)
                b2[j] = *reinterpret_cast<const unsigned long long*>(&Bs2[kk2][tx + 16 * j]);
#pragma unroll
            for (int i = 0; i < 4; i++)
#pragma unroll
                for (int j = 0; j < 4; j++)
                    acc[i][j] = fma2(a2[i], b2[j], acc[i][j]);
        }
        __syncthreads();
    }

#pragma unroll
    for (int i = 0; i < 4; i++) {
        int row = rowBase + ty * 4 + i;
        if (row >= M) continue;
#pragma unroll
        for (int j = 0; j < 4; j++) {
            int col = colBase + tx + 16 * j;
            if (col < N) {
                float v = f2sum(acc[i][j]);
                if (bias) v += bias[col];
                if (act == 1) v = ftanh(v);
                else if (act == 2) v = fsig(v);
                C[(size_t)row * N + col] = v;
            }
        }
    }
}

// ---------------------------------------------------------------------------
// LSTM v5: HMMA gate matmul. 16 clusters x 8 CTAs x 4 batches.
// Whh in REGISTERS as bf16 hi/lo m16k16 A-fragments (warp w owns rows 16w..16w+15
// of the CTA's 128 gate-rows). h exchanged as packed {bf16 hi, bf16 lo} u32 via
// st.async into pair-packed SMEM; B-fragments built with 2 LDS.64 per k-tile.
// 3-pass split MMA (Ah*Bh + Al*Bh + Ah*Bl) into 4 acc copies.
#define HP_STRIDE 132                 // u64 per batch (128 used + pad)
#define HP_BUF    (4 * HP_STRIDE)     // u64 per buffer = 528
// floats: mbar 4 | hp 2*528*2=2112 | gp 640 | c 128 | sk 2048 | an 2048
#define LSTM_SMEM ((4 + 2112 + 640 + 128 + 2048 + 2048) * 4)

__global__ void __cluster_dims__(8, 1, 1) __launch_bounds__(256, 1)
lstm_kernel(const int* __restrict__ skill, const int* __restrict__ answer,
            const float* __restrict__ Whh, float* __restrict__ out) {
    extern __shared__ float smem[];
    uint32_t smem_u32 = s2u(smem);
    uint32_t mbar_u32[2] = { smem_u32, smem_u32 + 8 };
    unsigned long long* hp = (unsigned long long*)(smem + 4);   // [2][4][132] u64
    float* gp  = smem + 4 + 2112;        // [128 rows][5] (pad 5)
    float* c_s = gp + 640;               // [128]
    int* sk_s  = (int*)(c_s + 128);      // [4][512]
    int* an_s  = sk_s + 4 * S_;          // [4][512]

    int tid  = threadIdx.x;
    int w    = tid >> 5;
    int l    = tid & 31;
    int rank = blockIdx.x & 7;
    int cid  = blockIdx.x >> 3;

    // ---- one-time: Whh -> bf16 hi/lo A-fragments in registers ----
    // warp w owns row_local 16w..16w+15; row_local = gate*32 + unit_local
    uint32_t ah[16][4], al[16][4];
    {
        int rl0 = 16 * w + (l >> 2);
        int rl1 = rl0 + 8;
        size_t rowA = (size_t)((rl0 >> 5) * H_ + rank * 32 + (rl0 & 31)) * H_;
        size_t rowB = (size_t)((rl1 >> 5) * H_ + rank * 32 + (rl1 & 31)) * H_;
#pragma unroll
        for (int t = 0; t < 16; t++) {
            int k = t * 16 + (l & 3) * 2;
            packhl(*(const float2*)(Whh + rowA + k),     ah[t][0], al[t][0]);
            packhl(*(const float2*)(Whh + rowB + k),     ah[t][1], al[t][1]);
            packhl(*(const float2*)(Whh + rowA + k + 8), ah[t][2], al[t][2]);
            packhl(*(const float2*)(Whh + rowB + k + 8), ah[t][3], al[t][3]);
        }
    }

    // zero hp (both buffers) -> initial h = 0
    for (int i = tid; i < 2 * HP_BUF; i += 256) hp[i] = 0ULL;
    if (tid < 128) c_s[tid] = 0.f;
    for (int i = tid; i < 4 * S_; i += 256) {
        int bb = i >> 9, ss = i & (S_ - 1);
        int ridx = (cid * 4 + bb) * S_ + ss;
        sk_s[i] = skill[ridx];
        an_s[i] = answer[ridx];
    }
    if (tid == 0) {
        MBAR_INIT(mbar_u32[0], 1);
        MBAR_INIT(mbar_u32[1], 1);
    }
    __syncthreads();
    asm volatile("barrier.cluster.arrive.aligned;" ::: "memory");
    asm volatile("barrier.cluster.wait.aligned;" ::: "memory");

    const int uu  = tid & 31;
    const int ubb = tid >> 5;            // valid for tid<128
    const int n4  = (l >> 2) & 3;        // B-fragment batch (dup for lanes>=16)

    // hoisted remote slot addresses (2 buffers x 8 ranks) + mbar deltas
    uint32_t radr[2][8];
    uint32_t mdel[2];
    if (tid < 128) {
#pragma unroll
        for (int buf = 0; buf < 2; buf++) {
            uint32_t slot = smem_u32 + 16 +
                (uint32_t)(buf * HP_BUF + ubb * HP_STRIDE + rank * 16 + (uu >> 1)) * 8 +
                (uu & 1) * 4;
#pragma unroll
            for (int c8 = 0; c8 < 8; c8++)
                asm("mapa.shared::cluster.u32 %0, %1, %2;"
                    : "=r"(radr[buf][c8]) : "r"(slot), "r"(c8));
            mdel[buf] = mbar_u32[buf] - slot;
        }
    }

    int ph[2] = {0, 0};

    for (int s = 0; s < S_; s++) {
        const int p = s & 1;
        const int q = p ^ 1;

        if (tid == 0) MBAR_EXPECT(mbar_u32[q], 4096);
        if (s > 0) {
            mbar_wait_cluster(mbar_u32[p], ph[p]);
            ph[p] ^= 1;
        }

        // prefetch P rows for update phase (overlaps with mma)
        float pv[4] = {0.f, 0.f, 0.f, 0.f};
        if (tid < 128) {
            int sk = sk_s[ubb * S_ + s];
            int an = an_s[ubb * S_ + s];
            const float* P = an ? g_P1 : g_P0;
            const float* Pb = P + (size_t)sk * G4 + 32 * rank + uu;
            pv[0] = __ldg(Pb);
            pv[1] = __ldg(Pb + H_);
            pv[2] = __ldg(Pb + 2 * H_);
            pv[3] = __ldg(Pb + 3 * H_);
        }

        // ---- HMMA gate matmul: acc[m16n8] over k=256 in 16 tiles, 3 passes ----
        const unsigned long long* hb = hp + p * HP_BUF + n4 * HP_STRIDE;
        float acc[4][4];
#pragma unroll
        for (int a = 0; a < 4; a++)
#pragma unroll
            for (int e = 0; e < 4; e++) acc[a][e] = 0.f;

#pragma unroll
        for (int t = 0; t < 16; t++) {
            int j0 = t * 8 + (l & 3);
            uint2 v0 = *(const uint2*)(hb + j0);       // {hiPair, loPair} k0,k0+1
            uint2 v1 = *(const uint2*)(hb + j0 + 4);   // k0+8,k0+9
            mma16816(acc[t & 3], ah[t], v0.x, v1.x);   // Wh * hh
            mma16816(acc[t & 3], al[t], v0.x, v1.x);   // Wl * hh
            mma16816(acc[t & 3], ah[t], v0.y, v1.y);   // Wh * hl
        }
        float gsum[4];
#pragma unroll
        for (int e = 0; e < 4; e++)
            gsum[e] = (acc[0][e] + acc[1][e]) + (acc[2][e] + acc[3][e]);

        // store gate sums: gp[row][batch] (row stride 5)
        if ((l & 3) < 2) {
            int n  = (l & 3) * 2;
            int r0 = 16 * w + (l >> 2);
            gp[r0 * 5 + n]           = gsum[0];
            gp[r0 * 5 + n + 1]       = gsum[1];
            gp[(r0 + 8) * 5 + n]     = gsum[2];
            gp[(r0 + 8) * 5 + n + 1] = gsum[3];
        }
        __syncthreads();

        // ---- update phase (threads 0-127: batch ubb, unit uu) ----
        if (tid < 128) {
            float v[4];
#pragma unroll
            for (int g = 0; g < 4; g++)
                v[g] = gp[(g * 32 + uu) * 5 + ubb] + pv[g];
            float ig = fsig(v[0]), fg = fsig(v[1]);
            float gg = ftanh(v[2]), og = fsig(v[3]);
            float c = fg * c_s[tid] + ig * gg;
            c_s[tid] = c;
            float h = og * ftanh(c);
            int b = cid * 4 + ubb;
            out[(size_t)b * S_ * H_ + (size_t)s * H_ + 32 * rank + uu] = h;

            // pack h -> {bf16 hi, bf16 lo}; pair-swap with neighbor lane
            __nv_bfloat16 hh = __float2bfloat16(h);
            float lr = h - __bfloat162float(hh);
            __nv_bfloat16 hl = __float2bfloat16(lr);
            uint32_t myhi = __bfloat16_as_ushort(hh);
            uint32_t mylo = __bfloat16_as_ushort(hl);
            uint32_t obhi = __shfl_xor_sync(0xFFFFFFFFu, myhi, 1);
            uint32_t oblo = __shfl_xor_sync(0xFFFFFFFFu, mylo, 1);
            uint32_t payload = (uu & 1) ? ((mylo << 16) | oblo)
                                        : ((obhi << 16) | myhi);
            const uint32_t* ra = radr[q];
            uint32_t md = mdel[q];
#pragma unroll
            for (int c8 = 0; c8 < 8; c8++)
                st_async_u32(ra[c8], payload, ra[c8] + md);
        }
    }

    // drain before smem teardown
    mbar_wait_cluster(mbar_u32[0], ph[0]);
}

// ---------------------------------------------------------------------------
__global__ void attdot_kernel(const float* __restrict__ simW) {
    int warp = (blockIdx.x * blockDim.x + threadIdx.x) >> 5;
    int lane = threadIdx.x & 31;
    if (warp >= MTOT) return;
    const float* rowp = g_tmp80 + (size_t)warp * AD;
    float v = rowp[lane] * simW[lane] + rowp[lane + 32] * simW[lane + 32];
    if (lane < 16) v += rowp[lane + 64] * simW[lane + 64];
#pragma unroll
    for (int off = 16; off > 0; off >>= 1)
        v += __shfl_down_sync(0xFFFFFFFFu, v, off);
    if (lane == 0) g_att[warp] = v;
}

// ---------------------------------------------------------------------------
// prefix-softmax attention; emits final = [attn_cum_1 | out] as bf16 hi/lo
__global__ void attnscan_kernel() {
    int b = blockIdx.x;
    int t = threadIdx.x;
    __shared__ float e_s[S_];
    __shared__ float dinv[S_];
    for (int s = t; s < S_; s += H_) e_s[s] = __expf(g_att[b * S_ + s]);
    __syncthreads();
    if (t == 0) {
        float run = 0.f;
        for (int s = 0; s < S_; s++) { run += e_s[s]; dinv[s] = __fdividef(1.0f, run); }
    }
    __syncthreads();

    const float* ob = g_out + (size_t)b * S_ * H_;
    float acc = 0.f, cum = 0.f;
    for (int s = 0; s < S_; s++) {
        float o = __ldg(ob + (size_t)s * H_ + t);
        acc = fmaf(e_s[s], o, acc);
        float ao = acc * dinv[s];
        size_t base = ((size_t)b * S_ + s) * IN_;
        __nv_bfloat16 ch = __float2bfloat16(cum);
        g_finH[base + t] = ch;
        g_finL[base + t] = __float2bfloat16(cum - __bfloat162float(ch));
        __nv_bfloat16 oh = __float2bfloat16(o);
        g_finH[base + H_ + t] = oh;
        g_finL[base + H_ + t] = __float2bfloat16(o - __bfloat162float(oh));
        cum += ao;
    }
}

// ---------------------------------------------------------------------------
// fc GEMM on HMMA (mma.sync bf16, hi/lo split, 3 terms)
#define FC_STAGE 65536
#define FC_SMEM (2 * FC_STAGE + 1024)

__global__ void __launch_bounds__(256, 1)
fcgemm_kernel(float* __restrict__ res) {
    extern __shared__ char dsm[];
    __shared__ float fcb_s[128];
    uint32_t sb = (s2u(dsm) + 1023u) & ~1023u;

    int tid = threadIdx.x;
    int wid = tid >> 5, lane = tid & 31;
    int ntile = blockIdx.x, mtile = blockIdx.y;
    size_t mBase = (size_t)mtile * 128;
    int nBase = ntile * 128;

    if (tid < 128) fcb_s[tid] = g_fcb[nBase + tid];

    const __nv_bfloat16* srcs[4] = {
        g_finH + mBase * IN_, g_finL + mBase * IN_,
        g_fwH + (size_t)nBase * IN_, g_fwL + (size_t)nBase * IN_ };

    auto stage = [&](int c) {
        uint32_t base = sb + (uint32_t)(c & 1) * FC_STAGE;
        int k0 = c * 64;
#pragma unroll
        for (int i = 0; i < 16; i++) {
            int idx = tid + 256 * i;
            int tile = idx >> 10;
            int w = idx & 1023;
            int rr = w >> 3, gg = w & 7;
            uint32_t dst = base + tile * 16384 + SWZ(w * 16);
            const __nv_bfloat16* src = srcs[tile] + (size_t)rr * IN_ + k0 + gg * 8;
            cpa16(dst, src);
        }
        CPA_COMMIT();
    };

    const int mrow0 = (wid & 1) * 64;
    const int ncol0 = (wid >> 1) * 32;

    float acc[4][4][4];
#pragma unroll
    for (int mi = 0; mi < 4; mi++)
#pragma unroll
        for (int nj = 0; nj < 4; nj++)
#pragma unroll
            for (int q = 0; q < 4; q++) acc[mi][nj][q] = 0.f;

    stage(0);
    stage(1);

    for (int c = 0; c < 8; c++) {
        if (c < 7) cpa_wait<1>(); else cpa_wait<0>();
        __syncthreads();
        uint32_t base = sb + (uint32_t)(c & 1) * FC_STAGE;

#pragma unroll
        for (int ks = 0; ks < 4; ks++) {
            int kw = ks * 16 + ((lane >> 4) << 3);
            uint32_t a_h[4][4], a_l[4][4];
#pragma unroll
            for (int mi = 0; mi < 4; mi++) {
                int row = mrow0 + mi * 16 + (lane & 15);
                uint32_t off = SWZ((uint32_t)(row * 128 + kw * 2));
                ldsm4(a_h[mi], base + off);
                ldsm4(a_l[mi], base + 16384 + off);
            }
            uint32_t b_h[2][4], b_l[2][4];
#pragma unroll
            for (int bj = 0; bj < 2; bj++) {
                int nrow = ncol0 + bj * 16 + (lane & 15);
                uint32_t off = SWZ((uint32_t)(nrow * 128 + kw * 2));
                ldsm4(b_h[bj], base + 32768 + off);
                ldsm4(b_l[bj], base + 49152 + off);
            }
#pragma unroll
            for (int mi = 0; mi < 4; mi++)
#pragma unroll
                for (int nj = 0; nj < 4; nj++) {
                    int bj = nj >> 1, sel = nj & 1;
                    mma16816(acc[mi][nj], a_h[mi], b_h[bj][sel], b_h[bj][sel + 2]);
                    mma16816(acc[mi][nj], a_l[mi], b_h[bj][sel], b_h[bj][sel + 2]);
                    mma16816(acc[mi][nj], a_h[mi], b_l[bj][sel], b_l[bj][sel + 2]);
                }
        }
        __syncthreads();
        if (c + 2 < 8) stage(c + 2);
    }

#pragma unroll
    for (int mi = 0; mi < 4; mi++) {
        int r0 = (int)mBase + mrow0 + mi * 16 + (lane >> 2);
#pragma unroll
        for (int nj = 0; nj < 4; nj++) {
            int lc = ncol0 + nj * 8 + (lane & 3) * 2;
            int col = nBase + lc;
            if (col < NC) {
                float b0 = fcb_s[lc], b1 = fcb_s[lc + 1];
                float2 v0 = make_float2(fsig(acc[mi][nj][0] + b0),
                                        fsig(acc[mi][nj][1] + b1));
                float2 v1 = make_float2(fsig(acc[mi][nj][2] + b0),
                                        fsig(acc[mi][nj][3] + b1));
                *reinterpret_cast<float2*>(res + (size_t)r0 * NC + col) = v0;
                *reinterpret_cast<float2*>(res + (size_t)(r0 + 8) * NC + col) = v1;
            }
        }
    }
}

// ---------------------------------------------------------------------------
extern "C" void kernel_launch(void* const* d_in, const int* in_sizes, int n_in,
                              void* d_out, int out_size) {
    const int*   skill      = (const int*)  d_in[0];
    const int*   answer     = (const int*)  d_in[1];
    const float* skill_emb  = (const float*)d_in[2];
    const float* answer_emb = (const float*)d_in[3];
    const float* Wih        = (const float*)d_in[4];
    const float* Whh        = (const float*)d_in[5];
    const float* bih        = (const float*)d_in[6];
    const float* bhh        = (const float*)d_in[7];
    const float* mlp_W      = (const float*)d_in[8];
    const float* mlp_b      = (const float*)d_in[9];
    const float* sim_W      = (const float*)d_in[10];
    const float* fc_W       = (const float*)d_in[11];
    const float* fc_b       = (const float*)d_in[12];

    float* res = (float*)d_out;
    float* sa  = (float*)d_out + RES_ELEMS;

    float* P1_p;  cudaGetSymbolAddress((void**)&P1_p,  g_P1);
    float* P0_p;  cudaGetSymbolAddress((void**)&P0_p,  g_P0);
    float* qb_p;  cudaGetSymbolAddress((void**)&qb_p,  g_qb);
    float* out_p; cudaGetSymbolAddress((void**)&out_p, g_out);
    float* t80_p; cudaGetSymbolAddress((void**)&t80_p, g_tmp80);

    cudaFuncSetAttribute(lstm_kernel,
                         cudaFuncAttributeMaxDynamicSharedMemorySize, LSTM_SMEM);
    cudaFuncSetAttribute(fcgemm_kernel,
                         cudaFuncAttributeMaxDynamicSharedMemorySize, FC_SMEM);

    qbias_kernel<<<8, 256>>>(Wih, answer_emb, bih, bhh);
    embed_kernel<<<MTOT, 256>>>(skill, answer, skill_emb, answer_emb, sa);
    convw_kernel<<<(1024 * IN_ + 255) / 256, 256>>>(fc_W, fc_b);

    {
        dim3 grid(G4 / 64, (1000 + 63) / 64);
        gemm_kernel<<<grid, 256>>>(skill_emb, H_, Wih,      IN_, qb_p + G4, P1_p,
                                   1000, G4, H_, 0);
        gemm_kernel<<<grid, 256>>>(skill_emb, H_, Wih + H_, IN_, qb_p,      P0_p,
                                   1000, G4, H_, 0);
    }

    lstm_kernel<<<128, 256, LSTM_SMEM>>>(skill, answer, Whh, out_p);

    {
        dim3 grid((AD + 63) / 64, MTOT / 64);
        gemm_kernel<<<grid, 256>>>(out_p, H_, mlp_W, H_, mlp_b, t80_p,
                                   MTOT, AD, H_, 1);
    }

    attdot_kernel<<<(MTOT * 32 + 255) / 256, 256>>>(sim_W);
    attnscan_kernel<<<B_, H_>>>();

    {
        dim3 grid(8, 256);   // ntile, mtile
        fcgemm_kernel<<<grid, 256, FC_SMEM>>>(res);
    }
}